// round 11
// baseline (speedup 1.0000x reference)
#include <cuda_runtime.h>
#include <cuda_fp16.h>
#include <math.h>
#include <stdint.h>

#define S 2048
#define DIM 2048
#define NH 16
#define NKV 8
#define HD 128
#define HID 5632
#define QKV_DIM ((NH + 2*NKV) * HD)   // 4096
#define VOFF ((NH + NKV) * HD)        // 3072
#define EPS 1e-5f

// ---------------- scratch ----------------
__device__ __align__(256) __half g_h16[(size_t)S * DIM];
__device__ __align__(256) __half g_qkv16[(size_t)S * QKV_DIM];
__device__ __align__(256) __half g_o16[(size_t)S * DIM];
__device__ __align__(256) __half g_gate16[(size_t)S * HID];
__device__ __align__(256) __half g_vt16[(size_t)NKV * HD * S];
__device__ __align__(256) __half g_wqkv16[(size_t)QKV_DIM * DIM];
__device__ __align__(256) __half g_wo16[(size_t)DIM * DIM];
__device__ __align__(256) __half g_w13_16[(size_t)2 * HID * DIM];  // interleaved (w1_j,w3_j)
__device__ __align__(256) __half g_w2_16[(size_t)DIM * HID];
__device__ float g_h2[(size_t)S * DIM];

// ---------------- helpers ----------------
__device__ __forceinline__ uint32_t sm2u(const void* p) {
    uint32_t a;
    asm("{ .reg .u64 t; cvta.to.shared.u64 t, %1; cvt.u32.u64 %0, t; }" : "=r"(a) : "l"(p));
    return a;
}

__device__ __forceinline__ uint32_t smoff(uint32_t m, uint32_t k) {
    return (m >> 1) * 128u
         + (((((m & 1u) << 2) | (k >> 3)) ^ ((m >> 1) & 7u)) << 4)
         + (k & 7u) * 2u;
}
// 256B rows (128 halves), 16B chunk swizzle
__device__ __forceinline__ uint32_t smoff256(uint32_t r, uint32_t chunk) {
    return r * 256u + (((chunk ^ (r & 7u)) & 15u) << 4);
}
// 128B rows (64 halves), 16B chunk swizzle
__device__ __forceinline__ uint32_t smoff128(uint32_t r, uint32_t chunk) {
    return r * 128u + (((chunk ^ (r & 7u)) & 7u) << 4);
}

__device__ __forceinline__ uint4 ldm4(uint32_t addr) {
    uint4 r;
    asm volatile("ldmatrix.sync.aligned.m8n8.x4.shared.b16 {%0,%1,%2,%3}, [%4];"
                 : "=r"(r.x), "=r"(r.y), "=r"(r.z), "=r"(r.w) : "r"(addr));
    return r;
}

__device__ __forceinline__ void mma_f16(float* c, const uint4& a, uint32_t b0, uint32_t b1) {
    asm volatile(
        "mma.sync.aligned.m16n8k16.row.col.f32.f16.f16.f32 "
        "{%0,%1,%2,%3}, {%4,%5,%6,%7}, {%8,%9}, {%0,%1,%2,%3};"
        : "+f"(c[0]), "+f"(c[1]), "+f"(c[2]), "+f"(c[3])
        : "r"(a.x), "r"(a.y), "r"(a.z), "r"(a.w), "r"(b0), "r"(b1));
}

__device__ __forceinline__ void cpasync16(uint32_t dst, const void* src) {
    asm volatile("cp.async.cg.shared.global [%0], [%1], 16;" :: "r"(dst), "l"(src) : "memory");
}
__device__ __forceinline__ void cpcommit() {
    asm volatile("cp.async.commit_group;" ::: "memory");
}
template<int N> __device__ __forceinline__ void cpwait() {
    asm volatile("cp.async.wait_group %0;" :: "n"(N) : "memory");
}

__device__ __forceinline__ uint32_t h2u(float a, float b) {
    __half2 h = __floats2half2_rn(a, b);
    return *reinterpret_cast<uint32_t*>(&h);
}
__device__ __forceinline__ void st2(float* p, float a, float b) {
    *reinterpret_cast<float2*>(p) = make_float2(a, b);
}
__device__ __forceinline__ void st2(__half* p, float a, float b) {
    *reinterpret_cast<__half2*>(p) = __floats2half2_rn(a, b);
}
__device__ __forceinline__ float wredsum(float v) {
    #pragma unroll
    for (int o = 16; o; o >>= 1) v += __shfl_xor_sync(0xffffffffu, v, o);
    return v;
}

// ---------------- fp16 cp.async NT GEMM (2x2 warps, 64x64 warp tiles) ----------------
#define BM 128
#define BN 128
#define BK 32
#define ATILE_B 8192
#define STAGE_B 16384
#define NSTAGE 4

template<typename OutT, bool SWIGLU>
__global__ void __launch_bounds__(128, 2)
gemm_cp(const __half* __restrict__ A, const __half* __restrict__ B, OutT* __restrict__ C,
        int K, int lda, int ldb, int ldc, const float* __restrict__ res)
{
    int bm = blockIdx.x * BM;
    int bn = blockIdx.y * BN;

    extern __shared__ unsigned char smraw[];
    uint32_t smB = (sm2u(smraw) + 1023) & ~1023u;

    int tid  = threadIdx.x;
    int lane = tid & 31;
    int warp = tid >> 5;
    int wm = warp >> 1;
    int wn = warp & 1;

    int nCh = K / BK;

    int pr  = tid >> 2;
    int kc0 = (tid & 3) * 8;
    const __half* Ag = A + (long long)bm * lda;
    const __half* Bg = B + (long long)bn * ldb;
    uint32_t so[4];
    #pragma unroll
    for (int q = 0; q < 4; ++q) so[q] = smoff(pr + 32 * q, kc0);

    auto issue = [&](int c) {
        uint32_t aB = smB + (c & (NSTAGE - 1)) * STAGE_B;
        uint32_t bB = aB + ATILE_B;
        int k0 = c * BK + kc0;
        #pragma unroll
        for (int q = 0; q < 4; ++q)
            cpasync16(aB + so[q], Ag + (long long)(pr + 32 * q) * lda + k0);
        #pragma unroll
        for (int q = 0; q < 4; ++q)
            cpasync16(bB + so[q], Bg + (long long)(pr + 32 * q) * ldb + k0);
        cpcommit();
    };

    uint32_t aAdr[4], bAdr[4];
    {
        int mi = lane >> 3;
        int ra = (lane & 7) + (mi & 1) * 8;
        int ka = (mi >> 1) * 8;
        #pragma unroll
        for (int g = 0; g < 4; ++g) aAdr[g] = smoff(wm * 64 + g * 16 + ra, ka);
        int rb = (lane & 7) + (mi >> 1) * 8;
        int kb = (mi & 1) * 8;
        #pragma unroll
        for (int g = 0; g < 4; ++g) bAdr[g] = smoff(wn * 64 + g * 16 + rb, kb);
    }

    float acc[4][8][4];
    #pragma unroll
    for (int a = 0; a < 4; ++a)
        #pragma unroll
        for (int b = 0; b < 8; ++b)
            #pragma unroll
            for (int c = 0; c < 4; ++c) acc[a][b][c] = 0.f;

    #pragma unroll
    for (int c = 0; c < 3; ++c) {
        if (c < nCh) issue(c);
        else cpcommit();
    }

    for (int it = 0; it < nCh; ++it) {
        cpwait<2>();
        __syncthreads();
        if (it + 3 < nCh) issue(it + 3);
        else cpcommit();

        uint32_t aB = smB + (it & (NSTAGE - 1)) * STAGE_B;
        uint32_t bB = aB + ATILE_B;

        #pragma unroll
        for (int ks = 0; ks < 2; ++ks) {
            uint32_t kx = ks ? 32u : 0u;
            uint4 av[4], bv[4];
            #pragma unroll
            for (int g = 0; g < 4; ++g) av[g] = ldm4(aB + (aAdr[g] ^ kx));
            #pragma unroll
            for (int g = 0; g < 4; ++g) bv[g] = ldm4(bB + (bAdr[g] ^ kx));
            #pragma unroll
            for (int mi = 0; mi < 4; ++mi) {
                #pragma unroll
                for (int nj = 0; nj < 8; ++nj) {
                    uint32_t b0 = (nj & 1) ? bv[nj >> 1].z : bv[nj >> 1].x;
                    uint32_t b1 = (nj & 1) ? bv[nj >> 1].w : bv[nj >> 1].y;
                    mma_f16(acc[mi][nj], av[mi], b0, b1);
                }
            }
        }
    }
    cpwait<0>();

    int grp = lane >> 2;
    int tg  = lane & 3;
    #pragma unroll
    for (int mi = 0; mi < 4; ++mi) {
        long long r0 = bm + wm * 64 + mi * 16 + grp;
        #pragma unroll
        for (int nj = 0; nj < 8; ++nj) {
            int cl = wn * 64 + nj * 8 + tg * 2;
            if (SWIGLU) {
                int p = (bn + cl) >> 1;
                float a0 = acc[mi][nj][0], b0v = acc[mi][nj][1];
                float a1 = acc[mi][nj][2], b1v = acc[mi][nj][3];
                float g0 = a0 * b0v / (1.f + expf(-a0));
                float g1 = a1 * b1v / (1.f + expf(-a1));
                __half* Ch = (__half*)C;
                Ch[r0 * ldc + p]       = __float2half_rn(g0);
                Ch[(r0 + 8) * ldc + p] = __float2half_rn(g1);
            } else {
                int c0 = bn + cl;
                float v0 = acc[mi][nj][0], v1 = acc[mi][nj][1];
                float v2 = acc[mi][nj][2], v3 = acc[mi][nj][3];
                if (res) {
                    float2 r01 = *reinterpret_cast<const float2*>(&res[r0 * ldc + c0]);
                    float2 r23 = *reinterpret_cast<const float2*>(&res[(r0 + 8) * ldc + c0]);
                    v0 += r01.x; v1 += r01.y; v2 += r23.x; v3 += r23.y;
                }
                st2(&C[r0 * ldc + c0],       v0, v1);
                st2(&C[(r0 + 8) * ldc + c0], v2, v3);
            }
        }
    }
}

// ---------------- fused flash attention (BQ=64, BK=64, 128 thr, 2 CTA/SM) ----------------
// grid (32 qb, 16 heads). Warp owns 16 query rows. K/V 64-key blocks
// double-buffered via cp.async. Online softmax in registers.
#define FA_SMQ 16384
#define FA_SMK 16384
#define FA_SMV 16384
#define FA_SMEM (FA_SMQ + 2 * FA_SMK + 2 * FA_SMV + 256)

__global__ void __launch_bounds__(128, 2)
flash_attn(const __half* __restrict__ qkv, const __half* __restrict__ vt,
           __half* __restrict__ o)
{
    int qb = 31 - blockIdx.x;          // heavy blocks first
    int h  = blockIdx.y;
    int nb = qb + 1;                   // 64-key blocks

    extern __shared__ unsigned char smraw[];
    uint32_t smQ = (sm2u(smraw) + 255) & ~255u;
    uint32_t smK = smQ + FA_SMQ;
    uint32_t smV = smK + 2 * FA_SMK;

    int tid  = threadIdx.x;
    int lane = tid & 31;
    int warp = tid >> 5;               // 0..3
    int wrow = warp * 16;
    int grp  = lane >> 2;
    int tg   = lane & 3;

    const __half* Qg = qkv + (size_t)(qb * 64) * QKV_DIM + h * HD;
    const __half* Kg = qkv + NH * HD + (h >> 1) * HD;        // [key][dim]
    const __half* Vg = vt + (size_t)((h >> 1) * HD) * S;     // [dim][key]

    // producers
    int prow = tid >> 1;               // 0..63
    int pc0  = (tid & 1) * 8;          // 0 or 8 (16B chunks)

    auto issueQ = [&]() {
        #pragma unroll
        for (int i = 0; i < 8; ++i) {
            int ch = pc0 + i;
            cpasync16(smQ + smoff256(prow, ch), Qg + (size_t)prow * QKV_DIM + ch * 8);
        }
    };
    auto issueKV = [&](int b) {
        uint32_t kB = smK + (b & 1) * FA_SMK;
        uint32_t vB = smV + (b & 1) * FA_SMV;
        #pragma unroll
        for (int i = 0; i < 8; ++i) {
            int ch = pc0 + i;
            cpasync16(kB + smoff256(prow, ch),
                      Kg + (size_t)(b * 64 + prow) * QKV_DIM + ch * 8);
        }
        // V: 128 dim-rows x 64 keys (128B rows); thread t -> row t, chunks 0..7
        #pragma unroll
        for (int ch = 0; ch < 8; ++ch) {
            cpasync16(vB + smoff128(tid, ch),
                      Vg + (size_t)tid * S + b * 64 + ch * 8);
        }
    };

    issueQ();
    issueKV(0);
    cpcommit();

    int mi   = lane >> 3;
    int frow = (lane & 7) + (mi & 1) * 8;
    int fkc  = (mi >> 1);
    int brow = (lane & 7) + (mi >> 1) * 8;
    int bkc  = (mi & 1);

    float m0 = -1e30f, m1 = -1e30f, l0 = 0.f, l1 = 0.f;
    float O[16][4];
    #pragma unroll
    for (int j = 0; j < 16; ++j)
        #pragma unroll
        for (int c = 0; c < 4; ++c) O[j][c] = 0.f;

    uint4 qf[8];
    const float CS = 0.1275447941f;    // (1/sqrt(128)) * log2(e)

    for (int b = 0; b < nb; ++b) {
        cpwait<0>();
        __syncthreads();

        if (b == 0) {
            #pragma unroll
            for (int ks = 0; ks < 8; ++ks)
                qf[ks] = ldm4(smQ + smoff256(wrow + frow, ks * 2 + fkc));
        }
        if (b + 1 < nb) { issueKV(b + 1); cpcommit(); }

        uint32_t kB = smK + (b & 1) * FA_SMK;
        uint32_t vB = smV + (b & 1) * FA_SMV;

        // ---- S = Q @ K^T  (16 x 64 per warp) ----
        float Sv[8][4];
        #pragma unroll
        for (int j = 0; j < 8; ++j)
            #pragma unroll
            for (int c = 0; c < 4; ++c) Sv[j][c] = 0.f;

        #pragma unroll
        for (int ks = 0; ks < 8; ++ks) {
            #pragma unroll
            for (int g = 0; g < 4; ++g) {
                uint4 bv = ldm4(kB + smoff256(g * 16 + brow, ks * 2 + bkc));
                mma_f16(Sv[2 * g],     qf[ks], bv.x, bv.y);
                mma_f16(Sv[2 * g + 1], qf[ks], bv.z, bv.w);
            }
        }

        // ---- causal mask (diagonal block) ----
        if (b == qb) {
            int r0 = wrow + grp;
            #pragma unroll
            for (int j = 0; j < 8; ++j) {
                int c0 = j * 8 + tg * 2;
                if (c0     > r0)     Sv[j][0] = -1e30f;
                if (c0 + 1 > r0)     Sv[j][1] = -1e30f;
                if (c0     > r0 + 8) Sv[j][2] = -1e30f;
                if (c0 + 1 > r0 + 8) Sv[j][3] = -1e30f;
            }
        }

        // ---- online softmax ----
        float bm0 = -1e30f, bm1 = -1e30f;
        #pragma unroll
        for (int j = 0; j < 8; ++j) {
            bm0 = fmaxf(bm0, fmaxf(Sv[j][0], Sv[j][1]));
            bm1 = fmaxf(bm1, fmaxf(Sv[j][2], Sv[j][3]));
        }
        bm0 = fmaxf(bm0, __shfl_xor_sync(0xffffffffu, bm0, 1));
        bm0 = fmaxf(bm0, __shfl_xor_sync(0xffffffffu, bm0, 2));
        bm1 = fmaxf(bm1, __shfl_xor_sync(0xffffffffu, bm1, 1));
        bm1 = fmaxf(bm1, __shfl_xor_sync(0xffffffffu, bm1, 2));

        float nm0 = fmaxf(m0, bm0), nm1 = fmaxf(m1, bm1);
        float sc0 = exp2f((m0 - nm0) * CS), sc1 = exp2f((m1 - nm1) * CS);
        m0 = nm0; m1 = nm1;

        float rs0 = 0.f, rs1 = 0.f;
        #pragma unroll
        for (int j = 0; j < 8; ++j) {
            Sv[j][0] = exp2f((Sv[j][0] - nm0) * CS); rs0 += Sv[j][0];
            Sv[j][1] = exp2f((Sv[j][1] - nm0) * CS); rs0 += Sv[j][1];
            Sv[j][2] = exp2f((Sv[j][2] - nm1) * CS); rs1 += Sv[j][2];
            Sv[j][3] = exp2f((Sv[j][3] - nm1) * CS); rs1 += Sv[j][3];
        }
        l0 = l0 * sc0 + rs0;
        l1 = l1 * sc1 + rs1;

        #pragma unroll
        for (int j = 0; j < 16; ++j) {
            O[j][0] *= sc0; O[j][1] *= sc0;
            O[j][2] *= sc1; O[j][3] *= sc1;
        }

        // ---- O += P @ V ----
        #pragma unroll
        for (int ks = 0; ks < 4; ++ks) {
            uint4 pa;
            pa.x = h2u(Sv[2 * ks][0],     Sv[2 * ks][1]);
            pa.y = h2u(Sv[2 * ks][2],     Sv[2 * ks][3]);
            pa.z = h2u(Sv[2 * ks + 1][0], Sv[2 * ks + 1][1]);
            pa.w = h2u(Sv[2 * ks + 1][2], Sv[2 * ks + 1][3]);
            #pragma unroll
            for (int g = 0; g < 8; ++g) {
                uint4 bv = ldm4(vB + smoff128(g * 16 + brow, ks * 2 + bkc));
                mma_f16(O[2 * g],     pa, bv.x, bv.y);
                mma_f16(O[2 * g + 1], pa, bv.z, bv.w);
            }
        }
    }

    // ---- normalize + write ----
    l0 += __shfl_xor_sync(0xffffffffu, l0, 1);
    l0 += __shfl_xor_sync(0xffffffffu, l0, 2);
    l1 += __shfl_xor_sync(0xffffffffu, l1, 1);
    l1 += __shfl_xor_sync(0xffffffffu, l1, 2);
    float inv0 = 1.f / l0, inv1 = 1.f / l1;

    __half* o0 = o + (size_t)(qb * 64 + wrow + grp) * DIM + h * HD;
    __half* o1 = o0 + 8 * DIM;
    #pragma unroll
    for (int j = 0; j < 16; ++j) {
        int c0 = j * 8 + tg * 2;
        st2(o0 + c0, O[j][0] * inv0, O[j][1] * inv0);
        st2(o1 + c0, O[j][2] * inv1, O[j][3] * inv1);
    }
}

// ---------------- fp32 -> fp16, ILP 4 ----------------
__global__ void f2h_kernel(const float* __restrict__ in, __half* __restrict__ out, long long n)
{
    long long i = ((long long)blockIdx.x * 256 + threadIdx.x) * 16;
    if (i >= n) return;
    float4 v[4];
    #pragma unroll
    for (int q = 0; q < 4; ++q)
        v[q] = *reinterpret_cast<const float4*>(in + i + q * 4);
    #pragma unroll
    for (int q = 0; q < 2; ++q) {
        uint4 o;
        o.x = h2u(v[2*q].x,   v[2*q].y);
        o.y = h2u(v[2*q].z,   v[2*q].w);
        o.z = h2u(v[2*q+1].x, v[2*q+1].y);
        o.w = h2u(v[2*q+1].z, v[2*q+1].w);
        *reinterpret_cast<uint4*>(out + i + q * 8) = o;
    }
}

// w13 interleave: out row 2j = w1 row j, row 2j+1 = w3 row j
__global__ void f2h_w13(const float* __restrict__ in, __half* __restrict__ out)
{
    long long g = ((long long)blockIdx.x * 256 + threadIdx.x) * 8;
    if (g >= (long long)HID * DIM) return;
    long long j = g / DIM;
    long long c = g - j * DIM;
    #pragma unroll
    for (int s = 0; s < 2; ++s) {
        const float* src = in + ((s ? HID : 0) + j) * (long long)DIM + c;
        float4 a = *reinterpret_cast<const float4*>(src);
        float4 b = *reinterpret_cast<const float4*>(src + 4);
        uint4 o;
        o.x = h2u(a.x, a.y); o.y = h2u(a.z, a.w);
        o.z = h2u(b.x, b.y); o.w = h2u(b.z, b.w);
        *reinterpret_cast<uint4*>(out + (2 * j + s) * (long long)DIM + c) = o;
    }
}

// ---------------- V transpose ----------------
__global__ void transpose_v(const __half* __restrict__ qkv, __half* __restrict__ vt)
{
    __shared__ float t[32][33];
    int s0 = blockIdx.x * 32;
    int d0 = blockIdx.y * 32;
    int tx = threadIdx.x, ty = threadIdx.y;
    #pragma unroll
    for (int j = 0; j < 32; j += 8)
        t[ty + j][tx] = __half2float(qkv[(long long)(s0 + ty + j) * QKV_DIM + VOFF + d0 + tx]);
    __syncthreads();
    #pragma unroll
    for (int j = 0; j < 32; j += 8)
        vt[(long long)(d0 + ty + j) * S + s0 + tx] = __float2half_rn(t[tx][ty + j]);
}

// ---------------- warp-per-row rmsnorm ----------------
__global__ void rmsnorm_h(const float* __restrict__ x, const float* __restrict__ w,
                          __half* __restrict__ out)
{
    int row  = blockIdx.x * 8 + (threadIdx.x >> 5);
    int lane = threadIdx.x & 31;
    const float* xr = x + (long long)row * DIM;

    float s = 0.f;
    float4 v[16];
    #pragma unroll
    for (int i = 0; i < 16; ++i) {
        v[i] = *reinterpret_cast<const float4*>(xr + lane * 4 + i * 128);
        s += v[i].x * v[i].x + v[i].y * v[i].y + v[i].z * v[i].z + v[i].w * v[i].w;
    }
    s = wredsum(s);
    float inv = rsqrtf(s / (float)DIM + EPS);

    __half* orow = out + (long long)row * DIM;
    #pragma unroll
    for (int i = 0; i < 16; ++i) {
        int c = lane * 4 + i * 128;
        uint2 o;
        o.x = h2u(v[i].x * inv * w[c],     v[i].y * inv * w[c + 1]);
        o.y = h2u(v[i].z * inv * w[c + 2], v[i].w * inv * w[c + 3]);
        *reinterpret_cast<uint2*>(orow + c) = o;
    }
}

// ---------------- warp-per-head layernorm + rope ----------------
__global__ void qknorm_rope_h(__half* __restrict__ qkv,
                              const float* __restrict__ qn_w, const float* __restrict__ qn_b,
                              const float* __restrict__ kn_w, const float* __restrict__ kn_b,
                              const float* __restrict__ fcos, const float* __restrict__ fsin)
{
    int s    = blockIdx.x;
    int hh   = blockIdx.y * 8 + (threadIdx.x >> 5);
    int lane = threadIdx.x & 31;
    bool isq = (hh < NH);
    int col  = isq ? hh * HD : NH * HD + (hh - NH) * HD;
    __half* p = qkv + (long long)s * QKV_DIM + col + lane * 4;
    const float* w = (isq ? qn_w : kn_w) + lane * 4;
    const float* b = (isq ? qn_b : kn_b) + lane * 4;

    uint2 raw = *reinterpret_cast<const uint2*>(p);
    __half2 h01 = *reinterpret_cast<__half2*>(&raw.x);
    __half2 h23 = *reinterpret_cast<__half2*>(&raw.y);
    float v0 = __half2float(h01.x), v1 = __half2float(h01.y);
    float v2 = __half2float(h23.x), v3 = __half2float(h23.y);

    float mean = wredsum(v0 + v1 + v2 + v3) * (1.f / HD);
    float d0 = v0 - mean, d1 = v1 - mean, d2 = v2 - mean, d3 = v3 - mean;
    float var = wredsum(d0*d0 + d1*d1 + d2*d2 + d3*d3) * (1.f / HD);
    float rs = rsqrtf(var + EPS);

    float n0 = d0 * rs * w[0] + b[0];
    float n1 = d1 * rs * w[1] + b[1];
    float n2 = d2 * rs * w[2] + b[2];
    float n3 = d3 * rs * w[3] + b[3];

    const float* fc = fcos + (long long)s * (HD / 2) + lane * 2;
    const float* fs = fsin + (long long)s * (HD / 2) + lane * 2;
    float c0 = fc[0], s0 = fs[0], c1 = fc[1], s1 = fs[1];

    uint2 o;
    o.x = h2u(n0 * c0 - n1 * s0, n0 * s0 + n1 * c0);
    o.y = h2u(n2 * c1 - n3 * s1, n2 * s1 + n3 * c1);
    *reinterpret_cast<uint2*>(p) = o;
}

// ---------------- launcher ----------------
extern "C" void kernel_launch(void* const* d_in, const int* in_sizes, int n_in,
                              void* d_out, int out_size)
{
    const float* x           = (const float*)d_in[0];
    const float* fcos        = (const float*)d_in[1];
    const float* fsin        = (const float*)d_in[2];
    const float* wqkv        = (const float*)d_in[4];
    const float* wo          = (const float*)d_in[5];
    const float* qn_w        = (const float*)d_in[6];
    const float* qn_b        = (const float*)d_in[7];
    const float* kn_w        = (const float*)d_in[8];
    const float* kn_b        = (const float*)d_in[9];
    const float* attn_norm_w = (const float*)d_in[10];
    const float* ffn_norm_w  = (const float*)d_in[11];
    const float* w13         = (const float*)d_in[12];
    const float* w2          = (const float*)d_in[13];
    float* out = (float*)d_out;

    __half *h16, *qkv16, *o16, *gate16, *vt16;
    __half *wqkv16, *wo16, *w13_16, *w2_16;
    float *h2;
    cudaGetSymbolAddress((void**)&h16,     g_h16);
    cudaGetSymbolAddress((void**)&qkv16,   g_qkv16);
    cudaGetSymbolAddress((void**)&o16,     g_o16);
    cudaGetSymbolAddress((void**)&gate16,  g_gate16);
    cudaGetSymbolAddress((void**)&vt16,    g_vt16);
    cudaGetSymbolAddress((void**)&wqkv16,  g_wqkv16);
    cudaGetSymbolAddress((void**)&wo16,    g_wo16);
    cudaGetSymbolAddress((void**)&w13_16,  g_w13_16);
    cudaGetSymbolAddress((void**)&w2_16,   g_w2_16);
    cudaGetSymbolAddress((void**)&h2,      g_h2);

    static cudaStream_t sW = nullptr, sT = nullptr;
    static cudaEvent_t evRoot = nullptr, evW = nullptr, evQ = nullptr, evT = nullptr;
    if (!sW) {
        cudaStreamCreateWithFlags(&sW, cudaStreamNonBlocking);
        cudaStreamCreateWithFlags(&sT, cudaStreamNonBlocking);
        cudaEventCreateWithFlags(&evRoot, cudaEventDisableTiming);
        cudaEventCreateWithFlags(&evW,    cudaEventDisableTiming);
        cudaEventCreateWithFlags(&evQ,    cudaEventDisableTiming);
        cudaEventCreateWithFlags(&evT,    cudaEventDisableTiming);
    }

    const int SMEM = NSTAGE * STAGE_B + 1024;
    cudaFuncSetAttribute((gemm_cp<float, false>),  cudaFuncAttributeMaxDynamicSharedMemorySize, SMEM);
    cudaFuncSetAttribute((gemm_cp<__half, false>), cudaFuncAttributeMaxDynamicSharedMemorySize, SMEM);
    cudaFuncSetAttribute((gemm_cp<__half, true>),  cudaFuncAttributeMaxDynamicSharedMemorySize, SMEM);
    cudaFuncSetAttribute(flash_attn, cudaFuncAttributeMaxDynamicSharedMemorySize, FA_SMEM);

    // fork: stream sW converts wo/w13/w2 while main stream runs qkv path
    cudaEventRecord(evRoot, 0);
    cudaStreamWaitEvent(sW, evRoot, 0);
    f2h_kernel<<<((long long)DIM * DIM) / (256 * 16), 256, 0, sW>>>(wo, wo16, (long long)DIM * DIM);
    f2h_w13<<<((long long)HID * DIM) / (256 * 8), 256, 0, sW>>>(w13, w13_16);
    f2h_kernel<<<((long long)DIM * HID) / (256 * 16), 256, 0, sW>>>(w2, w2_16, (long long)DIM * HID);
    cudaEventRecord(evW, sW);

    f2h_kernel<<<(QKV_DIM * (long long)DIM) / (256 * 16), 256>>>(wqkv, wqkv16, (long long)QKV_DIM * DIM);
    rmsnorm_h<<<S / 8, 256>>>(x, attn_norm_w, h16);

    gemm_cp<__half, false><<<dim3(S / BM, QKV_DIM / BN, 1), 128, SMEM>>>(
        h16, wqkv16, qkv16, DIM, DIM, DIM, QKV_DIM, nullptr);

    // fork: transpose_v in parallel with qknorm
    cudaEventRecord(evQ, 0);
    cudaStreamWaitEvent(sT, evQ, 0);
    transpose_v<<<dim3(S / 32, (NKV * HD) / 32), dim3(32, 8), 0, sT>>>(qkv16, vt16);
    cudaEventRecord(evT, sT);

    qknorm_rope_h<<<dim3(S, 3), 256>>>(qkv16, qn_w, qn_b, kn_w, kn_b, fcos, fsin);
    cudaStreamWaitEvent(0, evT, 0);

    // flash attention -> o16 (BQ=64, 512 CTAs, 2 CTA/SM)
    flash_attn<<<dim3(32, 16), 128, FA_SMEM>>>(qkv16, vt16, o16);

    cudaStreamWaitEvent(0, evW, 0);

    gemm_cp<float, false><<<dim3(S / BM, DIM / BN, 1), 128, SMEM>>>(
        o16, wo16, h2, DIM, DIM, DIM, DIM, x);

    rmsnorm_h<<<S / 8, 256>>>(h2, ffn_norm_w, h16);

    gemm_cp<__half, true><<<dim3(S / BM, (2 * HID) / BN, 1), 128, SMEM>>>(
        h16, w13_16, gate16, DIM, DIM, DIM, HID, nullptr);

    gemm_cp<float, false><<<dim3(S / BM, DIM / BN, 1), 128, SMEM>>>(
        gate16, w2_16, out, HID, HID, HID, DIM, h2);
}

// round 12
// speedup vs baseline: 1.0123x; 1.0123x over previous
#include <cuda_runtime.h>
#include <cuda_fp16.h>
#include <math.h>
#include <stdint.h>

#define S 2048
#define DIM 2048
#define NH 16
#define NKV 8
#define HD 128
#define HID 5632
#define QKV_DIM ((NH + 2*NKV) * HD)   // 4096
#define VOFF ((NH + NKV) * HD)        // 3072
#define EPS 1e-5f

// ---------------- scratch ----------------
__device__ __align__(256) __half g_h16[(size_t)S * DIM];
__device__ __align__(256) __half g_qkv16[(size_t)S * QKV_DIM];
__device__ __align__(256) __half g_o16[(size_t)S * DIM];
__device__ __align__(256) __half g_gate16[(size_t)S * HID];
__device__ __align__(256) __half g_vt16[(size_t)NKV * HD * S];
__device__ __align__(256) __half g_wqkv16[(size_t)QKV_DIM * DIM];
__device__ __align__(256) __half g_wo16[(size_t)DIM * DIM];
__device__ __align__(256) __half g_w13_16[(size_t)2 * HID * DIM];  // interleaved (w1_j,w3_j)
__device__ __align__(256) __half g_w2_16[(size_t)DIM * HID];
__device__ float g_h2[(size_t)S * DIM];

// ---------------- helpers ----------------
__device__ __forceinline__ uint32_t sm2u(const void* p) {
    uint32_t a;
    asm("{ .reg .u64 t; cvta.to.shared.u64 t, %1; cvt.u32.u64 %0, t; }" : "=r"(a) : "l"(p));
    return a;
}

__device__ __forceinline__ uint32_t smoff(uint32_t m, uint32_t k) {
    return (m >> 1) * 128u
         + (((((m & 1u) << 2) | (k >> 3)) ^ ((m >> 1) & 7u)) << 4)
         + (k & 7u) * 2u;
}
__device__ __forceinline__ uint32_t smoff256(uint32_t r, uint32_t chunk) {
    return r * 256u + (((chunk ^ (r & 7u)) & 15u) << 4);
}

__device__ __forceinline__ uint4 ldm4(uint32_t addr) {
    uint4 r;
    asm volatile("ldmatrix.sync.aligned.m8n8.x4.shared.b16 {%0,%1,%2,%3}, [%4];"
                 : "=r"(r.x), "=r"(r.y), "=r"(r.z), "=r"(r.w) : "r"(addr));
    return r;
}

__device__ __forceinline__ void mma_f16(float* c, const uint4& a, uint32_t b0, uint32_t b1) {
    asm volatile(
        "mma.sync.aligned.m16n8k16.row.col.f32.f16.f16.f32 "
        "{%0,%1,%2,%3}, {%4,%5,%6,%7}, {%8,%9}, {%0,%1,%2,%3};"
        : "+f"(c[0]), "+f"(c[1]), "+f"(c[2]), "+f"(c[3])
        : "r"(a.x), "r"(a.y), "r"(a.z), "r"(a.w), "r"(b0), "r"(b1));
}

__device__ __forceinline__ void cpasync16(uint32_t dst, const void* src) {
    asm volatile("cp.async.cg.shared.global [%0], [%1], 16;" :: "r"(dst), "l"(src) : "memory");
}
__device__ __forceinline__ void cpcommit() {
    asm volatile("cp.async.commit_group;" ::: "memory");
}
template<int N> __device__ __forceinline__ void cpwait() {
    asm volatile("cp.async.wait_group %0;" :: "n"(N) : "memory");
}

__device__ __forceinline__ uint32_t h2u(float a, float b) {
    __half2 h = __floats2half2_rn(a, b);
    return *reinterpret_cast<uint32_t*>(&h);
}
__device__ __forceinline__ void st2(float* p, float a, float b) {
    *reinterpret_cast<float2*>(p) = make_float2(a, b);
}
__device__ __forceinline__ void st2(__half* p, float a, float b) {
    *reinterpret_cast<__half2*>(p) = __floats2half2_rn(a, b);
}
__device__ __forceinline__ float wredsum(float v) {
    #pragma unroll
    for (int o = 16; o; o >>= 1) v += __shfl_xor_sync(0xffffffffu, v, o);
    return v;
}

// ---------------- fp16 cp.async NT GEMM (2x2 warps, 64x64 warp tiles) ----------------
#define BM 128
#define BN 128
#define BK 32
#define ATILE_B 8192
#define STAGE_B 16384
#define NSTAGE 4

template<typename OutT, bool SWIGLU>
__global__ void __launch_bounds__(128, 2)
gemm_cp(const __half* __restrict__ A, const __half* __restrict__ B, OutT* __restrict__ C,
        int K, int lda, int ldb, int ldc, const float* __restrict__ res)
{
    int bm = blockIdx.x * BM;
    int bn = blockIdx.y * BN;

    extern __shared__ unsigned char smraw[];
    uint32_t smB = (sm2u(smraw) + 1023) & ~1023u;

    int tid  = threadIdx.x;
    int lane = tid & 31;
    int warp = tid >> 5;
    int wm = warp >> 1;
    int wn = warp & 1;

    int nCh = K / BK;

    int pr  = tid >> 2;
    int kc0 = (tid & 3) * 8;
    const __half* Ag = A + (long long)bm * lda;
    const __half* Bg = B + (long long)bn * ldb;
    uint32_t so[4];
    #pragma unroll
    for (int q = 0; q < 4; ++q) so[q] = smoff(pr + 32 * q, kc0);

    auto issue = [&](int c) {
        uint32_t aB = smB + (c & (NSTAGE - 1)) * STAGE_B;
        uint32_t bB = aB + ATILE_B;
        int k0 = c * BK + kc0;
        #pragma unroll
        for (int q = 0; q < 4; ++q)
            cpasync16(aB + so[q], Ag + (long long)(pr + 32 * q) * lda + k0);
        #pragma unroll
        for (int q = 0; q < 4; ++q)
            cpasync16(bB + so[q], Bg + (long long)(pr + 32 * q) * ldb + k0);
        cpcommit();
    };

    uint32_t aAdr[4], bAdr[4];
    {
        int mi = lane >> 3;
        int ra = (lane & 7) + (mi & 1) * 8;
        int ka = (mi >> 1) * 8;
        #pragma unroll
        for (int g = 0; g < 4; ++g) aAdr[g] = smoff(wm * 64 + g * 16 + ra, ka);
        int rb = (lane & 7) + (mi >> 1) * 8;
        int kb = (mi & 1) * 8;
        #pragma unroll
        for (int g = 0; g < 4; ++g) bAdr[g] = smoff(wn * 64 + g * 16 + rb, kb);
    }

    float acc[4][8][4];
    #pragma unroll
    for (int a = 0; a < 4; ++a)
        #pragma unroll
        for (int b = 0; b < 8; ++b)
            #pragma unroll
            for (int c = 0; c < 4; ++c) acc[a][b][c] = 0.f;

    #pragma unroll
    for (int c = 0; c < 3; ++c) {
        if (c < nCh) issue(c);
        else cpcommit();
    }

    for (int it = 0; it < nCh; ++it) {
        cpwait<2>();
        __syncthreads();
        if (it + 3 < nCh) issue(it + 3);
        else cpcommit();

        uint32_t aB = smB + (it & (NSTAGE - 1)) * STAGE_B;
        uint32_t bB = aB + ATILE_B;

        #pragma unroll
        for (int ks = 0; ks < 2; ++ks) {
            uint32_t kx = ks ? 32u : 0u;
            uint4 av[4], bv[4];
            #pragma unroll
            for (int g = 0; g < 4; ++g) av[g] = ldm4(aB + (aAdr[g] ^ kx));
            #pragma unroll
            for (int g = 0; g < 4; ++g) bv[g] = ldm4(bB + (bAdr[g] ^ kx));
            #pragma unroll
            for (int mi = 0; mi < 4; ++mi) {
                #pragma unroll
                for (int nj = 0; nj < 8; ++nj) {
                    uint32_t b0 = (nj & 1) ? bv[nj >> 1].z : bv[nj >> 1].x;
                    uint32_t b1 = (nj & 1) ? bv[nj >> 1].w : bv[nj >> 1].y;
                    mma_f16(acc[mi][nj], av[mi], b0, b1);
                }
            }
        }
    }
    cpwait<0>();

    int grp = lane >> 2;
    int tg  = lane & 3;
    #pragma unroll
    for (int mi = 0; mi < 4; ++mi) {
        long long r0 = bm + wm * 64 + mi * 16 + grp;
        #pragma unroll
        for (int nj = 0; nj < 8; ++nj) {
            int cl = wn * 64 + nj * 8 + tg * 2;
            if (SWIGLU) {
                int p = (bn + cl) >> 1;
                float a0 = acc[mi][nj][0], b0v = acc[mi][nj][1];
                float a1 = acc[mi][nj][2], b1v = acc[mi][nj][3];
                float g0 = a0 * b0v / (1.f + expf(-a0));
                float g1 = a1 * b1v / (1.f + expf(-a1));
                __half* Ch = (__half*)C;
                Ch[r0 * ldc + p]       = __float2half_rn(g0);
                Ch[(r0 + 8) * ldc + p] = __float2half_rn(g1);
            } else {
                int c0 = bn + cl;
                float v0 = acc[mi][nj][0], v1 = acc[mi][nj][1];
                float v2 = acc[mi][nj][2], v3 = acc[mi][nj][3];
                if (res) {
                    float2 r01 = *reinterpret_cast<const float2*>(&res[r0 * ldc + c0]);
                    float2 r23 = *reinterpret_cast<const float2*>(&res[(r0 + 8) * ldc + c0]);
                    v0 += r01.x; v1 += r01.y; v2 += r23.x; v3 += r23.y;
                }
                st2(&C[r0 * ldc + c0],       v0, v1);
                st2(&C[(r0 + 8) * ldc + c0], v2, v3);
            }
        }
    }
}

// ---------------- fused flash attention (BQ=128, 256 thr — R10 proven shape) ----------------
__global__ void __launch_bounds__(256)
flash_attn(const __half* __restrict__ qkv, const __half* __restrict__ vt,
           __half* __restrict__ o)
{
    int qb = 15 - blockIdx.x;
    int h  = blockIdx.y;
    int nb = qb + 1;

    extern __shared__ unsigned char smraw[];
    uint32_t smQ = (sm2u(smraw) + 255) & ~255u;
    uint32_t smK = smQ + 32768;
    uint32_t smV = smK + 2 * 32768;

    int tid  = threadIdx.x;
    int lane = tid & 31;
    int warp = tid >> 5;
    int wrow = warp * 16;
    int grp  = lane >> 2;
    int tg   = lane & 3;

    const __half* Qg = qkv + (size_t)(qb * 128) * QKV_DIM + h * HD;
    const __half* Kg = qkv + NH * HD + (h >> 1) * HD;
    const __half* Vg = vt + (size_t)((h >> 1) * HD) * S;

    int prow = tid >> 1;
    int pc0  = (tid & 1) * 8;

    auto issueQ = [&]() {
        #pragma unroll
        for (int i = 0; i < 8; ++i) {
            int ch = pc0 + i;
            cpasync16(smQ + smoff256(prow, ch), Qg + (size_t)prow * QKV_DIM + ch * 8);
        }
    };
    auto issueKV = [&](int b) {
        uint32_t kB = smK + (b & 1) * 32768;
        uint32_t vB = smV + (b & 1) * 32768;
        #pragma unroll
        for (int i = 0; i < 8; ++i) {
            int ch = pc0 + i;
            uint32_t off = smoff256(prow, ch);
            cpasync16(kB + off, Kg + (size_t)(b * 128 + prow) * QKV_DIM + ch * 8);
            cpasync16(vB + off, Vg + (size_t)prow * S + b * 128 + ch * 8);
        }
    };

    issueQ();
    issueKV(0);
    cpcommit();

    int mi   = lane >> 3;
    int frow = (lane & 7) + (mi & 1) * 8;
    int fkc  = (mi >> 1);
    int brow = (lane & 7) + (mi >> 1) * 8;
    int bkc  = (mi & 1);

    float m0 = -1e30f, m1 = -1e30f, l0 = 0.f, l1 = 0.f;
    float O[16][4];
    #pragma unroll
    for (int j = 0; j < 16; ++j)
        #pragma unroll
        for (int c = 0; c < 4; ++c) O[j][c] = 0.f;

    uint4 qf[8];
    const float CS = 0.1275447941f;   // (1/sqrt(128)) * log2(e)

    for (int b = 0; b < nb; ++b) {
        cpwait<0>();
        __syncthreads();

        if (b == 0) {
            #pragma unroll
            for (int ks = 0; ks < 8; ++ks)
                qf[ks] = ldm4(smQ + smoff256(wrow + frow, ks * 2 + fkc));
        }
        if (b + 1 < nb) { issueKV(b + 1); cpcommit(); }

        uint32_t kB = smK + (b & 1) * 32768;
        uint32_t vB = smV + (b & 1) * 32768;

        float Sv[16][4];
        #pragma unroll
        for (int j = 0; j < 16; ++j)
            #pragma unroll
            for (int c = 0; c < 4; ++c) Sv[j][c] = 0.f;

        #pragma unroll
        for (int ks = 0; ks < 8; ++ks) {
            #pragma unroll
            for (int g = 0; g < 8; ++g) {
                uint4 bv = ldm4(kB + smoff256(g * 16 + brow, ks * 2 + bkc));
                mma_f16(Sv[2 * g],     qf[ks], bv.x, bv.y);
                mma_f16(Sv[2 * g + 1], qf[ks], bv.z, bv.w);
            }
        }

        if (b == qb) {
            int r0 = wrow + grp;
            #pragma unroll
            for (int j = 0; j < 16; ++j) {
                int c0 = j * 8 + tg * 2;
                if (c0     > r0)     Sv[j][0] = -1e30f;
                if (c0 + 1 > r0)     Sv[j][1] = -1e30f;
                if (c0     > r0 + 8) Sv[j][2] = -1e30f;
                if (c0 + 1 > r0 + 8) Sv[j][3] = -1e30f;
            }
        }

        float bm0 = -1e30f, bm1 = -1e30f;
        #pragma unroll
        for (int j = 0; j < 16; ++j) {
            bm0 = fmaxf(bm0, fmaxf(Sv[j][0], Sv[j][1]));
            bm1 = fmaxf(bm1, fmaxf(Sv[j][2], Sv[j][3]));
        }
        bm0 = fmaxf(bm0, __shfl_xor_sync(0xffffffffu, bm0, 1));
        bm0 = fmaxf(bm0, __shfl_xor_sync(0xffffffffu, bm0, 2));
        bm1 = fmaxf(bm1, __shfl_xor_sync(0xffffffffu, bm1, 1));
        bm1 = fmaxf(bm1, __shfl_xor_sync(0xffffffffu, bm1, 2));

        float nm0 = fmaxf(m0, bm0), nm1 = fmaxf(m1, bm1);
        float sc0 = exp2f((m0 - nm0) * CS), sc1 = exp2f((m1 - nm1) * CS);
        m0 = nm0; m1 = nm1;

        float rs0 = 0.f, rs1 = 0.f;
        #pragma unroll
        for (int j = 0; j < 16; ++j) {
            Sv[j][0] = exp2f((Sv[j][0] - nm0) * CS); rs0 += Sv[j][0];
            Sv[j][1] = exp2f((Sv[j][1] - nm0) * CS); rs0 += Sv[j][1];
            Sv[j][2] = exp2f((Sv[j][2] - nm1) * CS); rs1 += Sv[j][2];
            Sv[j][3] = exp2f((Sv[j][3] - nm1) * CS); rs1 += Sv[j][3];
        }
        l0 = l0 * sc0 + rs0;
        l1 = l1 * sc1 + rs1;

        #pragma unroll
        for (int j = 0; j < 16; ++j) {
            O[j][0] *= sc0; O[j][1] *= sc0;
            O[j][2] *= sc1; O[j][3] *= sc1;
        }

        #pragma unroll
        for (int ks = 0; ks < 8; ++ks) {
            uint4 pa;
            pa.x = h2u(Sv[2 * ks][0],     Sv[2 * ks][1]);
            pa.y = h2u(Sv[2 * ks][2],     Sv[2 * ks][3]);
            pa.z = h2u(Sv[2 * ks + 1][0], Sv[2 * ks + 1][1]);
            pa.w = h2u(Sv[2 * ks + 1][2], Sv[2 * ks + 1][3]);
            #pragma unroll
            for (int g = 0; g < 8; ++g) {
                uint4 bv = ldm4(vB + smoff256(g * 16 + brow, ks * 2 + bkc));
                mma_f16(O[2 * g],     pa, bv.x, bv.y);
                mma_f16(O[2 * g + 1], pa, bv.z, bv.w);
            }
        }
    }

    l0 += __shfl_xor_sync(0xffffffffu, l0, 1);
    l0 += __shfl_xor_sync(0xffffffffu, l0, 2);
    l1 += __shfl_xor_sync(0xffffffffu, l1, 1);
    l1 += __shfl_xor_sync(0xffffffffu, l1, 2);
    float inv0 = 1.f / l0, inv1 = 1.f / l1;

    __half* o0 = o + (size_t)(qb * 128 + wrow + grp) * DIM + h * HD;
    __half* o1 = o0 + 8 * DIM;
    #pragma unroll
    for (int j = 0; j < 16; ++j) {
        int c0 = j * 8 + tg * 2;
        st2(o0 + c0, O[j][0] * inv0, O[j][1] * inv0);
        st2(o1 + c0, O[j][2] * inv1, O[j][3] * inv1);
    }
}

// ---------------- fp32 -> fp16, ILP 8 (32 floats / thread) ----------------
__global__ void f2h_kernel(const float* __restrict__ in, __half* __restrict__ out, long long n)
{
    long long i = ((long long)blockIdx.x * 256 + threadIdx.x) * 32;
    if (i >= n) return;
    float4 v[8];
    #pragma unroll
    for (int q = 0; q < 8; ++q)
        v[q] = *reinterpret_cast<const float4*>(in + i + q * 4);
    #pragma unroll
    for (int q = 0; q < 4; ++q) {
        uint4 o;
        o.x = h2u(v[2*q].x,   v[2*q].y);
        o.y = h2u(v[2*q].z,   v[2*q].w);
        o.z = h2u(v[2*q+1].x, v[2*q+1].y);
        o.w = h2u(v[2*q+1].z, v[2*q+1].w);
        *reinterpret_cast<uint4*>(out + i + q * 8) = o;
    }
}

// w13 interleave: out row 2j = w1 row j, row 2j+1 = w3 row j
__global__ void f2h_w13(const float* __restrict__ in, __half* __restrict__ out)
{
    long long g = ((long long)blockIdx.x * 256 + threadIdx.x) * 8;
    if (g >= (long long)HID * DIM) return;
    long long j = g / DIM;
    long long c = g - j * DIM;
    #pragma unroll
    for (int s = 0; s < 2; ++s) {
        const float* src = in + ((s ? HID : 0) + j) * (long long)DIM + c;
        float4 a = *reinterpret_cast<const float4*>(src);
        float4 b = *reinterpret_cast<const float4*>(src + 4);
        uint4 o;
        o.x = h2u(a.x, a.y); o.y = h2u(a.z, a.w);
        o.z = h2u(b.x, b.y); o.w = h2u(b.z, b.w);
        *reinterpret_cast<uint4*>(out + (2 * j + s) * (long long)DIM + c) = o;
    }
}

// ---------------- V transpose ----------------
__global__ void transpose_v(const __half* __restrict__ qkv, __half* __restrict__ vt)
{
    __shared__ float t[32][33];
    int s0 = blockIdx.x * 32;
    int d0 = blockIdx.y * 32;
    int tx = threadIdx.x, ty = threadIdx.y;
    #pragma unroll
    for (int j = 0; j < 32; j += 8)
        t[ty + j][tx] = __half2float(qkv[(long long)(s0 + ty + j) * QKV_DIM + VOFF + d0 + tx]);
    __syncthreads();
    #pragma unroll
    for (int j = 0; j < 32; j += 8)
        vt[(long long)(d0 + ty + j) * S + s0 + tx] = __float2half_rn(t[tx][ty + j]);
}

// ---------------- warp-per-row rmsnorm ----------------
__global__ void rmsnorm_h(const float* __restrict__ x, const float* __restrict__ w,
                          __half* __restrict__ out)
{
    int row  = blockIdx.x * 8 + (threadIdx.x >> 5);
    int lane = threadIdx.x & 31;
    const float* xr = x + (long long)row * DIM;

    float s = 0.f;
    float4 v[16];
    #pragma unroll
    for (int i = 0; i < 16; ++i) {
        v[i] = *reinterpret_cast<const float4*>(xr + lane * 4 + i * 128);
        s += v[i].x * v[i].x + v[i].y * v[i].y + v[i].z * v[i].z + v[i].w * v[i].w;
    }
    s = wredsum(s);
    float inv = rsqrtf(s / (float)DIM + EPS);

    __half* orow = out + (long long)row * DIM;
    #pragma unroll
    for (int i = 0; i < 16; ++i) {
        int c = lane * 4 + i * 128;
        uint2 o;
        o.x = h2u(v[i].x * inv * w[c],     v[i].y * inv * w[c + 1]);
        o.y = h2u(v[i].z * inv * w[c + 2], v[i].w * inv * w[c + 3]);
        *reinterpret_cast<uint2*>(orow + c) = o;
    }
}

// ---------------- warp-per-head layernorm + rope ----------------
__global__ void qknorm_rope_h(__half* __restrict__ qkv,
                              const float* __restrict__ qn_w, const float* __restrict__ qn_b,
                              const float* __restrict__ kn_w, const float* __restrict__ kn_b,
                              const float* __restrict__ fcos, const float* __restrict__ fsin)
{
    int s    = blockIdx.x;
    int hh   = blockIdx.y * 8 + (threadIdx.x >> 5);
    int lane = threadIdx.x & 31;
    bool isq = (hh < NH);
    int col  = isq ? hh * HD : NH * HD + (hh - NH) * HD;
    __half* p = qkv + (long long)s * QKV_DIM + col + lane * 4;
    const float* w = (isq ? qn_w : kn_w) + lane * 4;
    const float* b = (isq ? qn_b : kn_b) + lane * 4;

    uint2 raw = *reinterpret_cast<const uint2*>(p);
    __half2 h01 = *reinterpret_cast<__half2*>(&raw.x);
    __half2 h23 = *reinterpret_cast<__half2*>(&raw.y);
    float v0 = __half2float(h01.x), v1 = __half2float(h01.y);
    float v2 = __half2float(h23.x), v3 = __half2float(h23.y);

    float mean = wredsum(v0 + v1 + v2 + v3) * (1.f / HD);
    float d0 = v0 - mean, d1 = v1 - mean, d2 = v2 - mean, d3 = v3 - mean;
    float var = wredsum(d0*d0 + d1*d1 + d2*d2 + d3*d3) * (1.f / HD);
    float rs = rsqrtf(var + EPS);

    float n0 = d0 * rs * w[0] + b[0];
    float n1 = d1 * rs * w[1] + b[1];
    float n2 = d2 * rs * w[2] + b[2];
    float n3 = d3 * rs * w[3] + b[3];

    const float* fc = fcos + (long long)s * (HD / 2) + lane * 2;
    const float* fs = fsin + (long long)s * (HD / 2) + lane * 2;
    float c0 = fc[0], s0 = fs[0], c1 = fc[1], s1 = fs[1];

    uint2 o;
    o.x = h2u(n0 * c0 - n1 * s0, n0 * s0 + n1 * c0);
    o.y = h2u(n2 * c1 - n3 * s1, n2 * s1 + n3 * c1);
    *reinterpret_cast<uint2*>(p) = o;
}

// ---------------- launcher ----------------
extern "C" void kernel_launch(void* const* d_in, const int* in_sizes, int n_in,
                              void* d_out, int out_size)
{
    const float* x           = (const float*)d_in[0];
    const float* fcos        = (const float*)d_in[1];
    const float* fsin        = (const float*)d_in[2];
    const float* wqkv        = (const float*)d_in[4];
    const float* wo          = (const float*)d_in[5];
    const float* qn_w        = (const float*)d_in[6];
    const float* qn_b        = (const float*)d_in[7];
    const float* kn_w        = (const float*)d_in[8];
    const float* kn_b        = (const float*)d_in[9];
    const float* attn_norm_w = (const float*)d_in[10];
    const float* ffn_norm_w  = (const float*)d_in[11];
    const float* w13         = (const float*)d_in[12];
    const float* w2          = (const float*)d_in[13];
    float* out = (float*)d_out;

    __half *h16, *qkv16, *o16, *gate16, *vt16;
    __half *wqkv16, *wo16, *w13_16, *w2_16;
    float *h2;
    cudaGetSymbolAddress((void**)&h16,     g_h16);
    cudaGetSymbolAddress((void**)&qkv16,   g_qkv16);
    cudaGetSymbolAddress((void**)&o16,     g_o16);
    cudaGetSymbolAddress((void**)&gate16,  g_gate16);
    cudaGetSymbolAddress((void**)&vt16,    g_vt16);
    cudaGetSymbolAddress((void**)&wqkv16,  g_wqkv16);
    cudaGetSymbolAddress((void**)&wo16,    g_wo16);
    cudaGetSymbolAddress((void**)&w13_16,  g_w13_16);
    cudaGetSymbolAddress((void**)&w2_16,   g_w2_16);
    cudaGetSymbolAddress((void**)&h2,      g_h2);

    static cudaStream_t sW = nullptr, sT = nullptr;
    static cudaEvent_t evRoot = nullptr, evW = nullptr, evWq = nullptr, evQ = nullptr, evT = nullptr;
    if (!sW) {
        cudaStreamCreateWithFlags(&sW, cudaStreamNonBlocking);
        cudaStreamCreateWithFlags(&sT, cudaStreamNonBlocking);
        cudaEventCreateWithFlags(&evRoot, cudaEventDisableTiming);
        cudaEventCreateWithFlags(&evW,    cudaEventDisableTiming);
        cudaEventCreateWithFlags(&evWq,   cudaEventDisableTiming);
        cudaEventCreateWithFlags(&evQ,    cudaEventDisableTiming);
        cudaEventCreateWithFlags(&evT,    cudaEventDisableTiming);
    }

    const int SMEM = NSTAGE * STAGE_B + 1024;
    const int FSMEM = 5 * 32768 + 256;
    cudaFuncSetAttribute((gemm_cp<float, false>),  cudaFuncAttributeMaxDynamicSharedMemorySize, SMEM);
    cudaFuncSetAttribute((gemm_cp<__half, false>), cudaFuncAttributeMaxDynamicSharedMemorySize, SMEM);
    cudaFuncSetAttribute((gemm_cp<__half, true>),  cudaFuncAttributeMaxDynamicSharedMemorySize, SMEM);
    cudaFuncSetAttribute(flash_attn, cudaFuncAttributeMaxDynamicSharedMemorySize, FSMEM);

    // ---- head: wqkv conversion runs ALONE on sT (critical path); rmsnorm in parallel ----
    cudaEventRecord(evRoot, 0);
    cudaStreamWaitEvent(sT, evRoot, 0);
    f2h_kernel<<<(QKV_DIM * (long long)DIM) / (256 * 32), 256, 0, sT>>>(
        wqkv, wqkv16, (long long)QKV_DIM * DIM);
    cudaEventRecord(evWq, sT);

    // sW: other weight conversions start AFTER wqkv is done (don't steal its BW);
    // they overlap the compute-bound qkv GEMM instead.
    cudaStreamWaitEvent(sW, evWq, 0);
    f2h_kernel<<<((long long)DIM * DIM) / (256 * 32), 256, 0, sW>>>(wo, wo16, (long long)DIM * DIM);
    f2h_w13<<<((long long)HID * DIM) / (256 * 8), 256, 0, sW>>>(w13, w13_16);
    f2h_kernel<<<((long long)DIM * HID) / (256 * 32), 256, 0, sW>>>(w2, w2_16, (long long)DIM * HID);
    cudaEventRecord(evW, sW);

    // main: rmsnorm (only needs x) runs concurrent with wqkv conversion
    rmsnorm_h<<<S / 8, 256>>>(x, attn_norm_w, h16);
    cudaStreamWaitEvent(0, evWq, 0);

    gemm_cp<__half, false><<<dim3(S / BM, QKV_DIM / BN, 1), 128, SMEM>>>(
        h16, wqkv16, qkv16, DIM, DIM, DIM, QKV_DIM, nullptr);

    // fork: transpose_v in parallel with qknorm
    cudaEventRecord(evQ, 0);
    cudaStreamWaitEvent(sT, evQ, 0);
    transpose_v<<<dim3(S / 32, (NKV * HD) / 32), dim3(32, 8), 0, sT>>>(qkv16, vt16);
    cudaEventRecord(evT, sT);

    qknorm_rope_h<<<dim3(S, 3), 256>>>(qkv16, qn_w, qn_b, kn_w, kn_b, fcos, fsin);
    cudaStreamWaitEvent(0, evT, 0);

    // flash attention -> o16 (BQ=128, proven R10 shape)
    flash_attn<<<dim3(16, 16), 256, FSMEM>>>(qkv16, vt16, o16);

    cudaStreamWaitEvent(0, evW, 0);

    gemm_cp<float, false><<<dim3(S / BM, DIM / BN, 1), 128, SMEM>>>(
        o16, wo16, h2, DIM, DIM, DIM, DIM, x);

    rmsnorm_h<<<S / 8, 256>>>(h2, ffn_norm_w, h16);

    gemm_cp<__half, true><<<dim3(S / BM, (2 * HID) / BN, 1), 128, SMEM>>>(
        h16, w13_16, gate16, DIM, DIM, DIM, HID, nullptr);

    gemm_cp<float, false><<<dim3(S / BM, DIM / BN, 1), 128, SMEM>>>(
        gate16, w2_16, out, HID, HID, HID, DIM, h2);
}

// round 13
// speedup vs baseline: 1.0440x; 1.0313x over previous
#include <cuda_runtime.h>
#include <cuda_fp16.h>
#include <math.h>
#include <stdint.h>

#define S 2048
#define DIM 2048
#define NH 16
#define NKV 8
#define HD 128
#define HID 5632
#define QKV_DIM ((NH + 2*NKV) * HD)   // 4096
#define VOFF ((NH + NKV) * HD)        // 3072
#define EPS 1e-5f

// ---------------- scratch ----------------
__device__ __align__(256) __half g_h16[(size_t)S * DIM];
__device__ __align__(256) __half g_qkv16[(size_t)S * QKV_DIM];
__device__ __align__(256) __half g_o16[(size_t)S * DIM];
__device__ __align__(256) __half g_gate16[(size_t)S * HID];
__device__ __align__(256) __half g_vt16[(size_t)NKV * HD * S];
__device__ __align__(256) __half g_wqkv16[(size_t)QKV_DIM * DIM];
__device__ __align__(256) __half g_wo16[(size_t)DIM * DIM];
__device__ __align__(256) __half g_w13_16[(size_t)2 * HID * DIM];  // interleaved (w1_j,w3_j)
__device__ __align__(256) __half g_w2_16[(size_t)DIM * HID];
__device__ float g_h2[(size_t)S * DIM];

// ---------------- helpers ----------------
__device__ __forceinline__ uint32_t sm2u(const void* p) {
    uint32_t a;
    asm("{ .reg .u64 t; cvta.to.shared.u64 t, %1; cvt.u32.u64 %0, t; }" : "=r"(a) : "l"(p));
    return a;
}

__device__ __forceinline__ uint32_t smoff(uint32_t m, uint32_t k) {
    return (m >> 1) * 128u
         + (((((m & 1u) << 2) | (k >> 3)) ^ ((m >> 1) & 7u)) << 4)
         + (k & 7u) * 2u;
}
__device__ __forceinline__ uint32_t smoff256(uint32_t r, uint32_t chunk) {
    return r * 256u + (((chunk ^ (r & 7u)) & 15u) << 4);
}

__device__ __forceinline__ uint4 ldm4(uint32_t addr) {
    uint4 r;
    asm volatile("ldmatrix.sync.aligned.m8n8.x4.shared.b16 {%0,%1,%2,%3}, [%4];"
                 : "=r"(r.x), "=r"(r.y), "=r"(r.z), "=r"(r.w) : "r"(addr));
    return r;
}

__device__ __forceinline__ void mma_f16(float* c, const uint4& a, uint32_t b0, uint32_t b1) {
    asm volatile(
        "mma.sync.aligned.m16n8k16.row.col.f32.f16.f16.f32 "
        "{%0,%1,%2,%3}, {%4,%5,%6,%7}, {%8,%9}, {%0,%1,%2,%3};"
        : "+f"(c[0]), "+f"(c[1]), "+f"(c[2]), "+f"(c[3])
        : "r"(a.x), "r"(a.y), "r"(a.z), "r"(a.w), "r"(b0), "r"(b1));
}

__device__ __forceinline__ void cpasync16(uint32_t dst, const void* src) {
    asm volatile("cp.async.cg.shared.global [%0], [%1], 16;" :: "r"(dst), "l"(src) : "memory");
}
__device__ __forceinline__ void cpcommit() {
    asm volatile("cp.async.commit_group;" ::: "memory");
}
template<int N> __device__ __forceinline__ void cpwait() {
    asm volatile("cp.async.wait_group %0;" :: "n"(N) : "memory");
}

__device__ __forceinline__ uint32_t h2u(float a, float b) {
    __half2 h = __floats2half2_rn(a, b);
    return *reinterpret_cast<uint32_t*>(&h);
}
__device__ __forceinline__ void st2(float* p, float a, float b) {
    *reinterpret_cast<float2*>(p) = make_float2(a, b);
}
__device__ __forceinline__ void st2(__half* p, float a, float b) {
    *reinterpret_cast<__half2*>(p) = __floats2half2_rn(a, b);
}
__device__ __forceinline__ float wredsum(float v) {
    #pragma unroll
    for (int o = 16; o; o >>= 1) v += __shfl_xor_sync(0xffffffffu, v, o);
    return v;
}

// ---------------- fp16 cp.async NT GEMM (2x2 warps, 64x64 warp tiles) ----------------
#define BM 128
#define BN 128
#define BK 32
#define ATILE_B 8192
#define STAGE_B 16384
#define NSTAGE 4

template<typename OutT, bool SWIGLU>
__global__ void __launch_bounds__(128, 2)
gemm_cp(const __half* __restrict__ A, const __half* __restrict__ B, OutT* __restrict__ C,
        int K, int lda, int ldb, int ldc, const float* __restrict__ res)
{
    int bm = blockIdx.x * BM;
    int bn = blockIdx.y * BN;

    extern __shared__ unsigned char smraw[];
    uint32_t smB = (sm2u(smraw) + 1023) & ~1023u;

    int tid  = threadIdx.x;
    int lane = tid & 31;
    int warp = tid >> 5;
    int wm = warp >> 1;
    int wn = warp & 1;

    int nCh = K / BK;

    int pr  = tid >> 2;
    int kc0 = (tid & 3) * 8;
    const __half* Ag = A + (long long)bm * lda;
    const __half* Bg = B + (long long)bn * ldb;
    uint32_t so[4];
    #pragma unroll
    for (int q = 0; q < 4; ++q) so[q] = smoff(pr + 32 * q, kc0);

    auto issue = [&](int c) {
        uint32_t aB = smB + (c & (NSTAGE - 1)) * STAGE_B;
        uint32_t bB = aB + ATILE_B;
        int k0 = c * BK + kc0;
        #pragma unroll
        for (int q = 0; q < 4; ++q)
            cpasync16(aB + so[q], Ag + (long long)(pr + 32 * q) * lda + k0);
        #pragma unroll
        for (int q = 0; q < 4; ++q)
            cpasync16(bB + so[q], Bg + (long long)(pr + 32 * q) * ldb + k0);
        cpcommit();
    };

    uint32_t aAdr[4], bAdr[4];
    {
        int mi = lane >> 3;
        int ra = (lane & 7) + (mi & 1) * 8;
        int ka = (mi >> 1) * 8;
        #pragma unroll
        for (int g = 0; g < 4; ++g) aAdr[g] = smoff(wm * 64 + g * 16 + ra, ka);
        int rb = (lane & 7) + (mi >> 1) * 8;
        int kb = (mi & 1) * 8;
        #pragma unroll
        for (int g = 0; g < 4; ++g) bAdr[g] = smoff(wn * 64 + g * 16 + rb, kb);
    }

    float acc[4][8][4];
    #pragma unroll
    for (int a = 0; a < 4; ++a)
        #pragma unroll
        for (int b = 0; b < 8; ++b)
            #pragma unroll
            for (int c = 0; c < 4; ++c) acc[a][b][c] = 0.f;

    #pragma unroll
    for (int c = 0; c < 3; ++c) {
        if (c < nCh) issue(c);
        else cpcommit();
    }

    for (int it = 0; it < nCh; ++it) {
        cpwait<2>();
        __syncthreads();
        if (it + 3 < nCh) issue(it + 3);
        else cpcommit();

        uint32_t aB = smB + (it & (NSTAGE - 1)) * STAGE_B;
        uint32_t bB = aB + ATILE_B;

        #pragma unroll
        for (int ks = 0; ks < 2; ++ks) {
            uint32_t kx = ks ? 32u : 0u;
            uint4 av[4], bv[4];
            #pragma unroll
            for (int g = 0; g < 4; ++g) av[g] = ldm4(aB + (aAdr[g] ^ kx));
            #pragma unroll
            for (int g = 0; g < 4; ++g) bv[g] = ldm4(bB + (bAdr[g] ^ kx));
            #pragma unroll
            for (int mi = 0; mi < 4; ++mi) {
                #pragma unroll
                for (int nj = 0; nj < 8; ++nj) {
                    uint32_t b0 = (nj & 1) ? bv[nj >> 1].z : bv[nj >> 1].x;
                    uint32_t b1 = (nj & 1) ? bv[nj >> 1].w : bv[nj >> 1].y;
                    mma_f16(acc[mi][nj], av[mi], b0, b1);
                }
            }
        }
    }
    cpwait<0>();

    int grp = lane >> 2;
    int tg  = lane & 3;
    #pragma unroll
    for (int mi = 0; mi < 4; ++mi) {
        long long r0 = bm + wm * 64 + mi * 16 + grp;
        #pragma unroll
        for (int nj = 0; nj < 8; ++nj) {
            int cl = wn * 64 + nj * 8 + tg * 2;
            if (SWIGLU) {
                int p = (bn + cl) >> 1;
                float a0 = acc[mi][nj][0], b0v = acc[mi][nj][1];
                float a1 = acc[mi][nj][2], b1v = acc[mi][nj][3];
                float g0 = a0 * b0v / (1.f + expf(-a0));
                float g1 = a1 * b1v / (1.f + expf(-a1));
                __half* Ch = (__half*)C;
                Ch[r0 * ldc + p]       = __float2half_rn(g0);
                Ch[(r0 + 8) * ldc + p] = __float2half_rn(g1);
            } else {
                int c0 = bn + cl;
                float v0 = acc[mi][nj][0], v1 = acc[mi][nj][1];
                float v2 = acc[mi][nj][2], v3 = acc[mi][nj][3];
                if (res) {
                    float2 r01 = *reinterpret_cast<const float2*>(&res[r0 * ldc + c0]);
                    float2 r23 = *reinterpret_cast<const float2*>(&res[(r0 + 8) * ldc + c0]);
                    v0 += r01.x; v1 += r01.y; v2 += r23.x; v3 += r23.y;
                }
                st2(&C[r0 * ldc + c0],       v0, v1);
                st2(&C[(r0 + 8) * ldc + c0], v2, v3);
            }
        }
    }
}

// ---------------- fused flash attention (BQ=128, 256 thr — proven shape) ----------------
__global__ void __launch_bounds__(256)
flash_attn(const __half* __restrict__ qkv, const __half* __restrict__ vt,
           __half* __restrict__ o)
{
    int qb = 15 - blockIdx.x;
    int h  = blockIdx.y;
    int nb = qb + 1;

    extern __shared__ unsigned char smraw[];
    uint32_t smQ = (sm2u(smraw) + 255) & ~255u;
    uint32_t smK = smQ + 32768;
    uint32_t smV = smK + 2 * 32768;

    int tid  = threadIdx.x;
    int lane = tid & 31;
    int warp = tid >> 5;
    int wrow = warp * 16;
    int grp  = lane >> 2;
    int tg   = lane & 3;

    const __half* Qg = qkv + (size_t)(qb * 128) * QKV_DIM + h * HD;
    const __half* Kg = qkv + NH * HD + (h >> 1) * HD;
    const __half* Vg = vt + (size_t)((h >> 1) * HD) * S;

    int prow = tid >> 1;
    int pc0  = (tid & 1) * 8;

    auto issueQ = [&]() {
        #pragma unroll
        for (int i = 0; i < 8; ++i) {
            int ch = pc0 + i;
            cpasync16(smQ + smoff256(prow, ch), Qg + (size_t)prow * QKV_DIM + ch * 8);
        }
    };
    auto issueKV = [&](int b) {
        uint32_t kB = smK + (b & 1) * 32768;
        uint32_t vB = smV + (b & 1) * 32768;
        #pragma unroll
        for (int i = 0; i < 8; ++i) {
            int ch = pc0 + i;
            uint32_t off = smoff256(prow, ch);
            cpasync16(kB + off, Kg + (size_t)(b * 128 + prow) * QKV_DIM + ch * 8);
            cpasync16(vB + off, Vg + (size_t)prow * S + b * 128 + ch * 8);
        }
    };

    issueQ();
    issueKV(0);
    cpcommit();

    int mi   = lane >> 3;
    int frow = (lane & 7) + (mi & 1) * 8;
    int fkc  = (mi >> 1);
    int brow = (lane & 7) + (mi >> 1) * 8;
    int bkc  = (mi & 1);

    float m0 = -1e30f, m1 = -1e30f, l0 = 0.f, l1 = 0.f;
    float O[16][4];
    #pragma unroll
    for (int j = 0; j < 16; ++j)
        #pragma unroll
        for (int c = 0; c < 4; ++c) O[j][c] = 0.f;

    uint4 qf[8];
    const float CS = 0.1275447941f;   // (1/sqrt(128)) * log2(e)

    for (int b = 0; b < nb; ++b) {
        cpwait<0>();
        __syncthreads();

        if (b == 0) {
            #pragma unroll
            for (int ks = 0; ks < 8; ++ks)
                qf[ks] = ldm4(smQ + smoff256(wrow + frow, ks * 2 + fkc));
        }
        if (b + 1 < nb) { issueKV(b + 1); cpcommit(); }

        uint32_t kB = smK + (b & 1) * 32768;
        uint32_t vB = smV + (b & 1) * 32768;

        float Sv[16][4];
        #pragma unroll
        for (int j = 0; j < 16; ++j)
            #pragma unroll
            for (int c = 0; c < 4; ++c) Sv[j][c] = 0.f;

        #pragma unroll
        for (int ks = 0; ks < 8; ++ks) {
            #pragma unroll
            for (int g = 0; g < 8; ++g) {
                uint4 bv = ldm4(kB + smoff256(g * 16 + brow, ks * 2 + bkc));
                mma_f16(Sv[2 * g],     qf[ks], bv.x, bv.y);
                mma_f16(Sv[2 * g + 1], qf[ks], bv.z, bv.w);
            }
        }

        if (b == qb) {
            int r0 = wrow + grp;
            #pragma unroll
            for (int j = 0; j < 16; ++j) {
                int c0 = j * 8 + tg * 2;
                if (c0     > r0)     Sv[j][0] = -1e30f;
                if (c0 + 1 > r0)     Sv[j][1] = -1e30f;
                if (c0     > r0 + 8) Sv[j][2] = -1e30f;
                if (c0 + 1 > r0 + 8) Sv[j][3] = -1e30f;
            }
        }

        float bm0 = -1e30f, bm1 = -1e30f;
        #pragma unroll
        for (int j = 0; j < 16; ++j) {
            bm0 = fmaxf(bm0, fmaxf(Sv[j][0], Sv[j][1]));
            bm1 = fmaxf(bm1, fmaxf(Sv[j][2], Sv[j][3]));
        }
        bm0 = fmaxf(bm0, __shfl_xor_sync(0xffffffffu, bm0, 1));
        bm0 = fmaxf(bm0, __shfl_xor_sync(0xffffffffu, bm0, 2));
        bm1 = fmaxf(bm1, __shfl_xor_sync(0xffffffffu, bm1, 1));
        bm1 = fmaxf(bm1, __shfl_xor_sync(0xffffffffu, bm1, 2));

        float nm0 = fmaxf(m0, bm0), nm1 = fmaxf(m1, bm1);
        float sc0 = exp2f((m0 - nm0) * CS), sc1 = exp2f((m1 - nm1) * CS);
        m0 = nm0; m1 = nm1;

        float rs0 = 0.f, rs1 = 0.f;
        #pragma unroll
        for (int j = 0; j < 16; ++j) {
            Sv[j][0] = exp2f((Sv[j][0] - nm0) * CS); rs0 += Sv[j][0];
            Sv[j][1] = exp2f((Sv[j][1] - nm0) * CS); rs0 += Sv[j][1];
            Sv[j][2] = exp2f((Sv[j][2] - nm1) * CS); rs1 += Sv[j][2];
            Sv[j][3] = exp2f((Sv[j][3] - nm1) * CS); rs1 += Sv[j][3];
        }
        l0 = l0 * sc0 + rs0;
        l1 = l1 * sc1 + rs1;

        #pragma unroll
        for (int j = 0; j < 16; ++j) {
            O[j][0] *= sc0; O[j][1] *= sc0;
            O[j][2] *= sc1; O[j][3] *= sc1;
        }

        #pragma unroll
        for (int ks = 0; ks < 8; ++ks) {
            uint4 pa;
            pa.x = h2u(Sv[2 * ks][0],     Sv[2 * ks][1]);
            pa.y = h2u(Sv[2 * ks][2],     Sv[2 * ks][3]);
            pa.z = h2u(Sv[2 * ks + 1][0], Sv[2 * ks + 1][1]);
            pa.w = h2u(Sv[2 * ks + 1][2], Sv[2 * ks + 1][3]);
            #pragma unroll
            for (int g = 0; g < 8; ++g) {
                uint4 bv = ldm4(vB + smoff256(g * 16 + brow, ks * 2 + bkc));
                mma_f16(O[2 * g],     pa, bv.x, bv.y);
                mma_f16(O[2 * g + 1], pa, bv.z, bv.w);
            }
        }
    }

    l0 += __shfl_xor_sync(0xffffffffu, l0, 1);
    l0 += __shfl_xor_sync(0xffffffffu, l0, 2);
    l1 += __shfl_xor_sync(0xffffffffu, l1, 1);
    l1 += __shfl_xor_sync(0xffffffffu, l1, 2);
    float inv0 = 1.f / l0, inv1 = 1.f / l1;

    __half* o0 = o + (size_t)(qb * 128 + wrow + grp) * DIM + h * HD;
    __half* o1 = o0 + 8 * DIM;
    #pragma unroll
    for (int j = 0; j < 16; ++j) {
        int c0 = j * 8 + tg * 2;
        st2(o0 + c0, O[j][0] * inv0, O[j][1] * inv0);
        st2(o1 + c0, O[j][2] * inv1, O[j][3] * inv1);
    }
}

// ---------------- fp32 -> fp16, ILP 4 (16 floats / thread — measured optimum) ----------------
__global__ void f2h_kernel(const float* __restrict__ in, __half* __restrict__ out, long long n)
{
    long long i = ((long long)blockIdx.x * 256 + threadIdx.x) * 16;
    if (i >= n) return;
    float4 v[4];
    #pragma unroll
    for (int q = 0; q < 4; ++q)
        v[q] = *reinterpret_cast<const float4*>(in + i + q * 4);
    #pragma unroll
    for (int q = 0; q < 2; ++q) {
        uint4 o;
        o.x = h2u(v[2*q].x,   v[2*q].y);
        o.y = h2u(v[2*q].z,   v[2*q].w);
        o.z = h2u(v[2*q+1].x, v[2*q+1].y);
        o.w = h2u(v[2*q+1].z, v[2*q+1].w);
        *reinterpret_cast<uint4*>(out + i + q * 8) = o;
    }
}

// w13 interleave: out row 2j = w1 row j, row 2j+1 = w3 row j
__global__ void f2h_w13(const float* __restrict__ in, __half* __restrict__ out)
{
    long long g = ((long long)blockIdx.x * 256 + threadIdx.x) * 8;
    if (g >= (long long)HID * DIM) return;
    long long j = g / DIM;
    long long c = g - j * DIM;
    #pragma unroll
    for (int s = 0; s < 2; ++s) {
        const float* src = in + ((s ? HID : 0) + j) * (long long)DIM + c;
        float4 a = *reinterpret_cast<const float4*>(src);
        float4 b = *reinterpret_cast<const float4*>(src + 4);
        uint4 o;
        o.x = h2u(a.x, a.y); o.y = h2u(a.z, a.w);
        o.z = h2u(b.x, b.y); o.w = h2u(b.z, b.w);
        *reinterpret_cast<uint4*>(out + (2 * j + s) * (long long)DIM + c) = o;
    }
}

// ---------------- V transpose ----------------
__global__ void transpose_v(const __half* __restrict__ qkv, __half* __restrict__ vt)
{
    __shared__ float t[32][33];
    int s0 = blockIdx.x * 32;
    int d0 = blockIdx.y * 32;
    int tx = threadIdx.x, ty = threadIdx.y;
    #pragma unroll
    for (int j = 0; j < 32; j += 8)
        t[ty + j][tx] = __half2float(qkv[(long long)(s0 + ty + j) * QKV_DIM + VOFF + d0 + tx]);
    __syncthreads();
    #pragma unroll
    for (int j = 0; j < 32; j += 8)
        vt[(long long)(d0 + ty + j) * S + s0 + tx] = __float2half_rn(t[tx][ty + j]);
}

// ---------------- warp-per-row rmsnorm ----------------
__global__ void rmsnorm_h(const float* __restrict__ x, const float* __restrict__ w,
                          __half* __restrict__ out)
{
    int row  = blockIdx.x * 8 + (threadIdx.x >> 5);
    int lane = threadIdx.x & 31;
    const float* xr = x + (long long)row * DIM;

    float s = 0.f;
    float4 v[16];
    #pragma unroll
    for (int i = 0; i < 16; ++i) {
        v[i] = *reinterpret_cast<const float4*>(xr + lane * 4 + i * 128);
        s += v[i].x * v[i].x + v[i].y * v[i].y + v[i].z * v[i].z + v[i].w * v[i].w;
    }
    s = wredsum(s);
    float inv = rsqrtf(s / (float)DIM + EPS);

    __half* orow = out + (long long)row * DIM;
    #pragma unroll
    for (int i = 0; i < 16; ++i) {
        int c = lane * 4 + i * 128;
        uint2 o;
        o.x = h2u(v[i].x * inv * w[c],     v[i].y * inv * w[c + 1]);
        o.y = h2u(v[i].z * inv * w[c + 2], v[i].w * inv * w[c + 3]);
        *reinterpret_cast<uint2*>(orow + c) = o;
    }
}

// ---------------- warp-per-head layernorm + rope ----------------
__global__ void qknorm_rope_h(__half* __restrict__ qkv,
                              const float* __restrict__ qn_w, const float* __restrict__ qn_b,
                              const float* __restrict__ kn_w, const float* __restrict__ kn_b,
                              const float* __restrict__ fcos, const float* __restrict__ fsin)
{
    int s    = blockIdx.x;
    int hh   = blockIdx.y * 8 + (threadIdx.x >> 5);
    int lane = threadIdx.x & 31;
    bool isq = (hh < NH);
    int col  = isq ? hh * HD : NH * HD + (hh - NH) * HD;
    __half* p = qkv + (long long)s * QKV_DIM + col + lane * 4;
    const float* w = (isq ? qn_w : kn_w) + lane * 4;
    const float* b = (isq ? qn_b : kn_b) + lane * 4;

    uint2 raw = *reinterpret_cast<const uint2*>(p);
    __half2 h01 = *reinterpret_cast<__half2*>(&raw.x);
    __half2 h23 = *reinterpret_cast<__half2*>(&raw.y);
    float v0 = __half2float(h01.x), v1 = __half2float(h01.y);
    float v2 = __half2float(h23.x), v3 = __half2float(h23.y);

    float mean = wredsum(v0 + v1 + v2 + v3) * (1.f / HD);
    float d0 = v0 - mean, d1 = v1 - mean, d2 = v2 - mean, d3 = v3 - mean;
    float var = wredsum(d0*d0 + d1*d1 + d2*d2 + d3*d3) * (1.f / HD);
    float rs = rsqrtf(var + EPS);

    float n0 = d0 * rs * w[0] + b[0];
    float n1 = d1 * rs * w[1] + b[1];
    float n2 = d2 * rs * w[2] + b[2];
    float n3 = d3 * rs * w[3] + b[3];

    const float* fc = fcos + (long long)s * (HD / 2) + lane * 2;
    const float* fs = fsin + (long long)s * (HD / 2) + lane * 2;
    float c0 = fc[0], s0 = fs[0], c1 = fc[1], s1 = fs[1];

    uint2 o;
    o.x = h2u(n0 * c0 - n1 * s0, n0 * s0 + n1 * c0);
    o.y = h2u(n2 * c1 - n3 * s1, n2 * s1 + n3 * c1);
    *reinterpret_cast<uint2*>(p) = o;
}

// ---------------- launcher ----------------
extern "C" void kernel_launch(void* const* d_in, const int* in_sizes, int n_in,
                              void* d_out, int out_size)
{
    const float* x           = (const float*)d_in[0];
    const float* fcos        = (const float*)d_in[1];
    const float* fsin        = (const float*)d_in[2];
    const float* wqkv        = (const float*)d_in[4];
    const float* wo          = (const float*)d_in[5];
    const float* qn_w        = (const float*)d_in[6];
    const float* qn_b        = (const float*)d_in[7];
    const float* kn_w        = (const float*)d_in[8];
    const float* kn_b        = (const float*)d_in[9];
    const float* attn_norm_w = (const float*)d_in[10];
    const float* ffn_norm_w  = (const float*)d_in[11];
    const float* w13         = (const float*)d_in[12];
    const float* w2          = (const float*)d_in[13];
    float* out = (float*)d_out;

    __half *h16, *qkv16, *o16, *gate16, *vt16;
    __half *wqkv16, *wo16, *w13_16, *w2_16;
    float *h2;
    cudaGetSymbolAddress((void**)&h16,     g_h16);
    cudaGetSymbolAddress((void**)&qkv16,   g_qkv16);
    cudaGetSymbolAddress((void**)&o16,     g_o16);
    cudaGetSymbolAddress((void**)&gate16,  g_gate16);
    cudaGetSymbolAddress((void**)&vt16,    g_vt16);
    cudaGetSymbolAddress((void**)&wqkv16,  g_wqkv16);
    cudaGetSymbolAddress((void**)&wo16,    g_wo16);
    cudaGetSymbolAddress((void**)&w13_16,  g_w13_16);
    cudaGetSymbolAddress((void**)&w2_16,   g_w2_16);
    cudaGetSymbolAddress((void**)&h2,      g_h2);

    static cudaStream_t sW = nullptr, sT = nullptr;
    static cudaEvent_t evRoot = nullptr, evW = nullptr, evWq = nullptr, evQ = nullptr, evT = nullptr;
    if (!sW) {
        cudaStreamCreateWithFlags(&sW, cudaStreamNonBlocking);
        cudaStreamCreateWithFlags(&sT, cudaStreamNonBlocking);
        cudaEventCreateWithFlags(&evRoot, cudaEventDisableTiming);
        cudaEventCreateWithFlags(&evW,    cudaEventDisableTiming);
        cudaEventCreateWithFlags(&evWq,   cudaEventDisableTiming);
        cudaEventCreateWithFlags(&evQ,    cudaEventDisableTiming);
        cudaEventCreateWithFlags(&evT,    cudaEventDisableTiming);
    }

    const int SMEM = NSTAGE * STAGE_B + 1024;
    const int FSMEM = 5 * 32768 + 256;
    cudaFuncSetAttribute((gemm_cp<float, false>),  cudaFuncAttributeMaxDynamicSharedMemorySize, SMEM);
    cudaFuncSetAttribute((gemm_cp<__half, false>), cudaFuncAttributeMaxDynamicSharedMemorySize, SMEM);
    cudaFuncSetAttribute((gemm_cp<__half, true>),  cudaFuncAttributeMaxDynamicSharedMemorySize, SMEM);
    cudaFuncSetAttribute(flash_attn, cudaFuncAttributeMaxDynamicSharedMemorySize, FSMEM);

    // ---- head: wqkv conversion runs ALONE on sT (critical path); rmsnorm in parallel ----
    cudaEventRecord(evRoot, 0);
    cudaStreamWaitEvent(sT, evRoot, 0);
    f2h_kernel<<<(QKV_DIM * (long long)DIM) / (256 * 16), 256, 0, sT>>>(
        wqkv, wqkv16, (long long)QKV_DIM * DIM);
    cudaEventRecord(evWq, sT);

    // sW: other weight conversions start AFTER wqkv (overlap the compute-bound qkv GEMM)
    cudaStreamWaitEvent(sW, evWq, 0);
    f2h_kernel<<<((long long)DIM * DIM) / (256 * 16), 256, 0, sW>>>(wo, wo16, (long long)DIM * DIM);
    f2h_w13<<<((long long)HID * DIM) / (256 * 8), 256, 0, sW>>>(w13, w13_16);
    f2h_kernel<<<((long long)DIM * HID) / (256 * 16), 256, 0, sW>>>(w2, w2_16, (long long)DIM * HID);
    cudaEventRecord(evW, sW);

    // main: rmsnorm runs concurrent with wqkv conversion
    rmsnorm_h<<<S / 8, 256>>>(x, attn_norm_w, h16);
    cudaStreamWaitEvent(0, evWq, 0);

    gemm_cp<__half, false><<<dim3(S / BM, QKV_DIM / BN, 1), 128, SMEM>>>(
        h16, wqkv16, qkv16, DIM, DIM, DIM, QKV_DIM, nullptr);

    // fork: transpose_v in parallel with qknorm
    cudaEventRecord(evQ, 0);
    cudaStreamWaitEvent(sT, evQ, 0);
    transpose_v<<<dim3(S / 32, (NKV * HD) / 32), dim3(32, 8), 0, sT>>>(qkv16, vt16);
    cudaEventRecord(evT, sT);

    qknorm_rope_h<<<dim3(S, 3), 256>>>(qkv16, qn_w, qn_b, kn_w, kn_b, fcos, fsin);
    cudaStreamWaitEvent(0, evT, 0);

    // flash attention -> o16
    flash_attn<<<dim3(16, 16), 256, FSMEM>>>(qkv16, vt16, o16);

    cudaStreamWaitEvent(0, evW, 0);

    gemm_cp<float, false><<<dim3(S / BM, DIM / BN, 1), 128, SMEM>>>(
        o16, wo16, h2, DIM, DIM, DIM, DIM, x);

    rmsnorm_h<<<S / 8, 256>>>(h2, ffn_norm_w, h16);

    gemm_cp<__half, true><<<dim3(S / BM, (2 * HID) / BN, 1), 128, SMEM>>>(
        h16, w13_16, gate16, DIM, DIM, DIM, HID, nullptr);

    gemm_cp<float, false><<<dim3(S / BM, DIM / BN, 1), 128, SMEM>>>(
        gate16, w2_16, out, HID, HID, HID, DIM, h2);
}

// round 14
// speedup vs baseline: 1.0505x; 1.0062x over previous
#include <cuda_runtime.h>
#include <cuda_fp16.h>
#include <math.h>
#include <stdint.h>

#define S 2048
#define DIM 2048
#define NH 16
#define NKV 8
#define HD 128
#define HID 5632
#define QKV_DIM ((NH + 2*NKV) * HD)   // 4096
#define VOFF ((NH + NKV) * HD)        // 3072
#define EPS 1e-5f

// ---------------- scratch ----------------
__device__ __align__(256) __half g_h16[(size_t)S * DIM];
__device__ __align__(256) __half g_qkv16[(size_t)S * QKV_DIM];
__device__ __align__(256) __half g_o16[(size_t)S * DIM];
__device__ __align__(256) __half g_gate16[(size_t)S * HID];
__device__ __align__(256) __half g_vt16[(size_t)NKV * HD * S];
__device__ __align__(256) __half g_wqkv16[(size_t)QKV_DIM * DIM];
__device__ __align__(256) __half g_wo16[(size_t)DIM * DIM];
__device__ __align__(256) __half g_w13_16[(size_t)2 * HID * DIM];  // interleaved (w1_j,w3_j)
__device__ __align__(256) __half g_w2_16[(size_t)DIM * HID];
__device__ float g_h2[(size_t)S * DIM];

// ---------------- helpers ----------------
__device__ __forceinline__ uint32_t sm2u(const void* p) {
    uint32_t a;
    asm("{ .reg .u64 t; cvta.to.shared.u64 t, %1; cvt.u32.u64 %0, t; }" : "=r"(a) : "l"(p));
    return a;
}

__device__ __forceinline__ uint32_t smoff(uint32_t m, uint32_t k) {
    return (m >> 1) * 128u
         + (((((m & 1u) << 2) | (k >> 3)) ^ ((m >> 1) & 7u)) << 4)
         + (k & 7u) * 2u;
}
__device__ __forceinline__ uint32_t smoff256(uint32_t r, uint32_t chunk) {
    return r * 256u + (((chunk ^ (r & 7u)) & 15u) << 4);
}

__device__ __forceinline__ uint4 ldm4(uint32_t addr) {
    uint4 r;
    asm volatile("ldmatrix.sync.aligned.m8n8.x4.shared.b16 {%0,%1,%2,%3}, [%4];"
                 : "=r"(r.x), "=r"(r.y), "=r"(r.z), "=r"(r.w) : "r"(addr));
    return r;
}

__device__ __forceinline__ void mma_f16(float* c, const uint4& a, uint32_t b0, uint32_t b1) {
    asm volatile(
        "mma.sync.aligned.m16n8k16.row.col.f32.f16.f16.f32 "
        "{%0,%1,%2,%3}, {%4,%5,%6,%7}, {%8,%9}, {%0,%1,%2,%3};"
        : "+f"(c[0]), "+f"(c[1]), "+f"(c[2]), "+f"(c[3])
        : "r"(a.x), "r"(a.y), "r"(a.z), "r"(a.w), "r"(b0), "r"(b1));
}

__device__ __forceinline__ void cpasync16(uint32_t dst, const void* src) {
    asm volatile("cp.async.cg.shared.global [%0], [%1], 16;" :: "r"(dst), "l"(src) : "memory");
}
__device__ __forceinline__ void cpcommit() {
    asm volatile("cp.async.commit_group;" ::: "memory");
}
template<int N> __device__ __forceinline__ void cpwait() {
    asm volatile("cp.async.wait_group %0;" :: "n"(N) : "memory");
}

__device__ __forceinline__ uint32_t h2u(float a, float b) {
    __half2 h = __floats2half2_rn(a, b);
    return *reinterpret_cast<uint32_t*>(&h);
}
__device__ __forceinline__ void st2(float* p, float a, float b) {
    *reinterpret_cast<float2*>(p) = make_float2(a, b);
}
__device__ __forceinline__ void st2(__half* p, float a, float b) {
    *reinterpret_cast<__half2*>(p) = __floats2half2_rn(a, b);
}
__device__ __forceinline__ float wredsum(float v) {
    #pragma unroll
    for (int o = 16; o; o >>= 1) v += __shfl_xor_sync(0xffffffffu, v, o);
    return v;
}

// ---------------- fp16 cp.async NT GEMM (2x2 warps, 64x64 warp tiles) ----------------
#define BM 128
#define BN 128
#define BK 32
#define ATILE_B 8192
#define STAGE_B 16384
#define NSTAGE 4

template<typename OutT, bool SWIGLU>
__global__ void __launch_bounds__(128, 2)
gemm_cp(const __half* __restrict__ A, const __half* __restrict__ B, OutT* __restrict__ C,
        int K, int lda, int ldb, int ldc, const float* __restrict__ res)
{
    int bm = blockIdx.x * BM;
    int bn = blockIdx.y * BN;

    extern __shared__ unsigned char smraw[];
    uint32_t smB = (sm2u(smraw) + 1023) & ~1023u;

    int tid  = threadIdx.x;
    int lane = tid & 31;
    int warp = tid >> 5;
    int wm = warp >> 1;
    int wn = warp & 1;

    int nCh = K / BK;

    int pr  = tid >> 2;
    int kc0 = (tid & 3) * 8;
    const __half* Ag = A + (long long)bm * lda;
    const __half* Bg = B + (long long)bn * ldb;
    uint32_t so[4];
    #pragma unroll
    for (int q = 0; q < 4; ++q) so[q] = smoff(pr + 32 * q, kc0);

    auto issue = [&](int c) {
        uint32_t aB = smB + (c & (NSTAGE - 1)) * STAGE_B;
        uint32_t bB = aB + ATILE_B;
        int k0 = c * BK + kc0;
        #pragma unroll
        for (int q = 0; q < 4; ++q)
            cpasync16(aB + so[q], Ag + (long long)(pr + 32 * q) * lda + k0);
        #pragma unroll
        for (int q = 0; q < 4; ++q)
            cpasync16(bB + so[q], Bg + (long long)(pr + 32 * q) * ldb + k0);
        cpcommit();
    };

    uint32_t aAdr[4], bAdr[4];
    {
        int mi = lane >> 3;
        int ra = (lane & 7) + (mi & 1) * 8;
        int ka = (mi >> 1) * 8;
        #pragma unroll
        for (int g = 0; g < 4; ++g) aAdr[g] = smoff(wm * 64 + g * 16 + ra, ka);
        int rb = (lane & 7) + (mi >> 1) * 8;
        int kb = (mi & 1) * 8;
        #pragma unroll
        for (int g = 0; g < 4; ++g) bAdr[g] = smoff(wn * 64 + g * 16 + rb, kb);
    }

    float acc[4][8][4];
    #pragma unroll
    for (int a = 0; a < 4; ++a)
        #pragma unroll
        for (int b = 0; b < 8; ++b)
            #pragma unroll
            for (int c = 0; c < 4; ++c) acc[a][b][c] = 0.f;

    #pragma unroll
    for (int c = 0; c < 3; ++c) {
        if (c < nCh) issue(c);
        else cpcommit();
    }

    for (int it = 0; it < nCh; ++it) {
        cpwait<2>();
        __syncthreads();
        if (it + 3 < nCh) issue(it + 3);
        else cpcommit();

        uint32_t aB = smB + (it & (NSTAGE - 1)) * STAGE_B;
        uint32_t bB = aB + ATILE_B;

        #pragma unroll
        for (int ks = 0; ks < 2; ++ks) {
            uint32_t kx = ks ? 32u : 0u;
            uint4 av[4], bv[4];
            #pragma unroll
            for (int g = 0; g < 4; ++g) av[g] = ldm4(aB + (aAdr[g] ^ kx));
            #pragma unroll
            for (int g = 0; g < 4; ++g) bv[g] = ldm4(bB + (bAdr[g] ^ kx));
            #pragma unroll
            for (int mi = 0; mi < 4; ++mi) {
                #pragma unroll
                for (int nj = 0; nj < 8; ++nj) {
                    uint32_t b0 = (nj & 1) ? bv[nj >> 1].z : bv[nj >> 1].x;
                    uint32_t b1 = (nj & 1) ? bv[nj >> 1].w : bv[nj >> 1].y;
                    mma_f16(acc[mi][nj], av[mi], b0, b1);
                }
            }
        }
    }
    cpwait<0>();

    int grp = lane >> 2;
    int tg  = lane & 3;

    if (SWIGLU) {
        // ---- smem-staged coalesced epilogue ----
        // scatter fp16 gate values into a [128][72] padded smem tile, then
        // copy out row-major as 16B stores (fully coalesced).
        __syncthreads();   // pipeline smem now dead; safe to reuse
        __half* buf = reinterpret_cast<__half*>(smraw);
        #pragma unroll
        for (int mi = 0; mi < 4; ++mi) {
            int lr = wm * 64 + mi * 16 + grp;
            #pragma unroll
            for (int nj = 0; nj < 8; ++nj) {
                int pl = wn * 32 + nj * 4 + tg;
                float a0 = acc[mi][nj][0], b0v = acc[mi][nj][1];
                float a1 = acc[mi][nj][2], b1v = acc[mi][nj][3];
                buf[lr * 72 + pl]       = __float2half_rn(a0 * b0v / (1.f + expf(-a0)));
                buf[(lr + 8) * 72 + pl] = __float2half_rn(a1 * b1v / (1.f + expf(-a1)));
            }
        }
        __syncthreads();
        __half* Ch = (__half*)C;
        __half* dst = Ch + (long long)(bm + tid) * ldc + (bn >> 1);
        const __half* srcb = buf + tid * 72;
        #pragma unroll
        for (int q = 0; q < 8; ++q)
            *reinterpret_cast<uint4*>(dst + q * 8) =
                *reinterpret_cast<const uint4*>(srcb + q * 8);
    } else {
        #pragma unroll
        for (int mi = 0; mi < 4; ++mi) {
            long long r0 = bm + wm * 64 + mi * 16 + grp;
            #pragma unroll
            for (int nj = 0; nj < 8; ++nj) {
                int c0 = bn + wn * 64 + nj * 8 + tg * 2;
                float v0 = acc[mi][nj][0], v1 = acc[mi][nj][1];
                float v2 = acc[mi][nj][2], v3 = acc[mi][nj][3];
                if (res) {
                    float2 r01 = *reinterpret_cast<const float2*>(&res[r0 * ldc + c0]);
                    float2 r23 = *reinterpret_cast<const float2*>(&res[(r0 + 8) * ldc + c0]);
                    v0 += r01.x; v1 += r01.y; v2 += r23.x; v3 += r23.y;
                }
                st2(&C[r0 * ldc + c0],       v0, v1);
                st2(&C[(r0 + 8) * ldc + c0], v2, v3);
            }
        }
    }
}

// ---------------- fused flash attention (BQ=128, 256 thr — proven shape) ----------------
__global__ void __launch_bounds__(256)
flash_attn(const __half* __restrict__ qkv, const __half* __restrict__ vt,
           __half* __restrict__ o)
{
    int qb = 15 - blockIdx.x;
    int h  = blockIdx.y;
    int nb = qb + 1;

    extern __shared__ unsigned char smraw[];
    uint32_t smQ = (sm2u(smraw) + 255) & ~255u;
    uint32_t smK = smQ + 32768;
    uint32_t smV = smK + 2 * 32768;

    int tid  = threadIdx.x;
    int lane = tid & 31;
    int warp = tid >> 5;
    int wrow = warp * 16;
    int grp  = lane >> 2;
    int tg   = lane & 3;

    const __half* Qg = qkv + (size_t)(qb * 128) * QKV_DIM + h * HD;
    const __half* Kg = qkv + NH * HD + (h >> 1) * HD;
    const __half* Vg = vt + (size_t)((h >> 1) * HD) * S;

    int prow = tid >> 1;
    int pc0  = (tid & 1) * 8;

    auto issueQ = [&]() {
        #pragma unroll
        for (int i = 0; i < 8; ++i) {
            int ch = pc0 + i;
            cpasync16(smQ + smoff256(prow, ch), Qg + (size_t)prow * QKV_DIM + ch * 8);
        }
    };
    auto issueKV = [&](int b) {
        uint32_t kB = smK + (b & 1) * 32768;
        uint32_t vB = smV + (b & 1) * 32768;
        #pragma unroll
        for (int i = 0; i < 8; ++i) {
            int ch = pc0 + i;
            uint32_t off = smoff256(prow, ch);
            cpasync16(kB + off, Kg + (size_t)(b * 128 + prow) * QKV_DIM + ch * 8);
            cpasync16(vB + off, Vg + (size_t)prow * S + b * 128 + ch * 8);
        }
    };

    issueQ();
    issueKV(0);
    cpcommit();

    int mi   = lane >> 3;
    int frow = (lane & 7) + (mi & 1) * 8;
    int fkc  = (mi >> 1);
    int brow = (lane & 7) + (mi >> 1) * 8;
    int bkc  = (mi & 1);

    float m0 = -1e30f, m1 = -1e30f, l0 = 0.f, l1 = 0.f;
    float O[16][4];
    #pragma unroll
    for (int j = 0; j < 16; ++j)
        #pragma unroll
        for (int c = 0; c < 4; ++c) O[j][c] = 0.f;

    uint4 qf[8];
    const float CS = 0.1275447941f;   // (1/sqrt(128)) * log2(e)

    for (int b = 0; b < nb; ++b) {
        cpwait<0>();
        __syncthreads();

        if (b == 0) {
            #pragma unroll
            for (int ks = 0; ks < 8; ++ks)
                qf[ks] = ldm4(smQ + smoff256(wrow + frow, ks * 2 + fkc));
        }
        if (b + 1 < nb) { issueKV(b + 1); cpcommit(); }

        uint32_t kB = smK + (b & 1) * 32768;
        uint32_t vB = smV + (b & 1) * 32768;

        float Sv[16][4];
        #pragma unroll
        for (int j = 0; j < 16; ++j)
            #pragma unroll
            for (int c = 0; c < 4; ++c) Sv[j][c] = 0.f;

        #pragma unroll
        for (int ks = 0; ks < 8; ++ks) {
            #pragma unroll
            for (int g = 0; g < 8; ++g) {
                uint4 bv = ldm4(kB + smoff256(g * 16 + brow, ks * 2 + bkc));
                mma_f16(Sv[2 * g],     qf[ks], bv.x, bv.y);
                mma_f16(Sv[2 * g + 1], qf[ks], bv.z, bv.w);
            }
        }

        if (b == qb) {
            int r0 = wrow + grp;
            #pragma unroll
            for (int j = 0; j < 16; ++j) {
                int c0 = j * 8 + tg * 2;
                if (c0     > r0)     Sv[j][0] = -1e30f;
                if (c0 + 1 > r0)     Sv[j][1] = -1e30f;
                if (c0     > r0 + 8) Sv[j][2] = -1e30f;
                if (c0 + 1 > r0 + 8) Sv[j][3] = -1e30f;
            }
        }

        float bm0 = -1e30f, bm1 = -1e30f;
        #pragma unroll
        for (int j = 0; j < 16; ++j) {
            bm0 = fmaxf(bm0, fmaxf(Sv[j][0], Sv[j][1]));
            bm1 = fmaxf(bm1, fmaxf(Sv[j][2], Sv[j][3]));
        }
        bm0 = fmaxf(bm0, __shfl_xor_sync(0xffffffffu, bm0, 1));
        bm0 = fmaxf(bm0, __shfl_xor_sync(0xffffffffu, bm0, 2));
        bm1 = fmaxf(bm1, __shfl_xor_sync(0xffffffffu, bm1, 1));
        bm1 = fmaxf(bm1, __shfl_xor_sync(0xffffffffu, bm1, 2));

        float nm0 = fmaxf(m0, bm0), nm1 = fmaxf(m1, bm1);
        float sc0 = exp2f((m0 - nm0) * CS), sc1 = exp2f((m1 - nm1) * CS);
        m0 = nm0; m1 = nm1;

        float rs0 = 0.f, rs1 = 0.f;
        #pragma unroll
        for (int j = 0; j < 16; ++j) {
            Sv[j][0] = exp2f((Sv[j][0] - nm0) * CS); rs0 += Sv[j][0];
            Sv[j][1] = exp2f((Sv[j][1] - nm0) * CS); rs0 += Sv[j][1];
            Sv[j][2] = exp2f((Sv[j][2] - nm1) * CS); rs1 += Sv[j][2];
            Sv[j][3] = exp2f((Sv[j][3] - nm1) * CS); rs1 += Sv[j][3];
        }
        l0 = l0 * sc0 + rs0;
        l1 = l1 * sc1 + rs1;

        #pragma unroll
        for (int j = 0; j < 16; ++j) {
            O[j][0] *= sc0; O[j][1] *= sc0;
            O[j][2] *= sc1; O[j][3] *= sc1;
        }

        #pragma unroll
        for (int ks = 0; ks < 8; ++ks) {
            uint4 pa;
            pa.x = h2u(Sv[2 * ks][0],     Sv[2 * ks][1]);
            pa.y = h2u(Sv[2 * ks][2],     Sv[2 * ks][3]);
            pa.z = h2u(Sv[2 * ks + 1][0], Sv[2 * ks + 1][1]);
            pa.w = h2u(Sv[2 * ks + 1][2], Sv[2 * ks + 1][3]);
            #pragma unroll
            for (int g = 0; g < 8; ++g) {
                uint4 bv = ldm4(vB + smoff256(g * 16 + brow, ks * 2 + bkc));
                mma_f16(O[2 * g],     pa, bv.x, bv.y);
                mma_f16(O[2 * g + 1], pa, bv.z, bv.w);
            }
        }
    }

    l0 += __shfl_xor_sync(0xffffffffu, l0, 1);
    l0 += __shfl_xor_sync(0xffffffffu, l0, 2);
    l1 += __shfl_xor_sync(0xffffffffu, l1, 1);
    l1 += __shfl_xor_sync(0xffffffffu, l1, 2);
    float inv0 = 1.f / l0, inv1 = 1.f / l1;

    __half* o0 = o + (size_t)(qb * 128 + wrow + grp) * DIM + h * HD;
    __half* o1 = o0 + 8 * DIM;
    #pragma unroll
    for (int j = 0; j < 16; ++j) {
        int c0 = j * 8 + tg * 2;
        st2(o0 + c0, O[j][0] * inv0, O[j][1] * inv0);
        st2(o1 + c0, O[j][2] * inv1, O[j][3] * inv1);
    }
}

// ---------------- fp32 -> fp16, ILP 4 (measured optimum) ----------------
__global__ void f2h_kernel(const float* __restrict__ in, __half* __restrict__ out, long long n)
{
    long long i = ((long long)blockIdx.x * 256 + threadIdx.x) * 16;
    if (i >= n) return;
    float4 v[4];
    #pragma unroll
    for (int q = 0; q < 4; ++q)
        v[q] = *reinterpret_cast<const float4*>(in + i + q * 4);
    #pragma unroll
    for (int q = 0; q < 2; ++q) {
        uint4 o;
        o.x = h2u(v[2*q].x,   v[2*q].y);
        o.y = h2u(v[2*q].z,   v[2*q].w);
        o.z = h2u(v[2*q+1].x, v[2*q+1].y);
        o.w = h2u(v[2*q+1].z, v[2*q+1].w);
        *reinterpret_cast<uint4*>(out + i + q * 8) = o;
    }
}

// w13 interleave: out row 2j = w1 row j, row 2j+1 = w3 row j
__global__ void f2h_w13(const float* __restrict__ in, __half* __restrict__ out)
{
    long long g = ((long long)blockIdx.x * 256 + threadIdx.x) * 8;
    if (g >= (long long)HID * DIM) return;
    long long j = g / DIM;
    long long c = g - j * DIM;
    #pragma unroll
    for (int s = 0; s < 2; ++s) {
        const float* src = in + ((s ? HID : 0) + j) * (long long)DIM + c;
        float4 a = *reinterpret_cast<const float4*>(src);
        float4 b = *reinterpret_cast<const float4*>(src + 4);
        uint4 o;
        o.x = h2u(a.x, a.y); o.y = h2u(a.z, a.w);
        o.z = h2u(b.x, b.y); o.w = h2u(b.z, b.w);
        *reinterpret_cast<uint4*>(out + (2 * j + s) * (long long)DIM + c) = o;
    }
}

// ---------------- V transpose ----------------
__global__ void transpose_v(const __half* __restrict__ qkv, __half* __restrict__ vt)
{
    __shared__ float t[32][33];
    int s0 = blockIdx.x * 32;
    int d0 = blockIdx.y * 32;
    int tx = threadIdx.x, ty = threadIdx.y;
    #pragma unroll
    for (int j = 0; j < 32; j += 8)
        t[ty + j][tx] = __half2float(qkv[(long long)(s0 + ty + j) * QKV_DIM + VOFF + d0 + tx]);
    __syncthreads();
    #pragma unroll
    for (int j = 0; j < 32; j += 8)
        vt[(long long)(d0 + ty + j) * S + s0 + tx] = __float2half_rn(t[tx][ty + j]);
}

// ---------------- warp-per-row rmsnorm ----------------
__global__ void rmsnorm_h(const float* __restrict__ x, const float* __restrict__ w,
                          __half* __restrict__ out)
{
    int row  = blockIdx.x * 8 + (threadIdx.x >> 5);
    int lane = threadIdx.x & 31;
    const float* xr = x + (long long)row * DIM;

    float s = 0.f;
    float4 v[16];
    #pragma unroll
    for (int i = 0; i < 16; ++i) {
        v[i] = *reinterpret_cast<const float4*>(xr + lane * 4 + i * 128);
        s += v[i].x * v[i].x + v[i].y * v[i].y + v[i].z * v[i].z + v[i].w * v[i].w;
    }
    s = wredsum(s);
    float inv = rsqrtf(s / (float)DIM + EPS);

    __half* orow = out + (long long)row * DIM;
    #pragma unroll
    for (int i = 0; i < 16; ++i) {
        int c = lane * 4 + i * 128;
        uint2 o;
        o.x = h2u(v[i].x * inv * w[c],     v[i].y * inv * w[c + 1]);
        o.y = h2u(v[i].z * inv * w[c + 2], v[i].w * inv * w[c + 3]);
        *reinterpret_cast<uint2*>(orow + c) = o;
    }
}

// ---------------- warp-per-head layernorm + rope ----------------
__global__ void qknorm_rope_h(__half* __restrict__ qkv,
                              const float* __restrict__ qn_w, const float* __restrict__ qn_b,
                              const float* __restrict__ kn_w, const float* __restrict__ kn_b,
                              const float* __restrict__ fcos, const float* __restrict__ fsin)
{
    int s    = blockIdx.x;
    int hh   = blockIdx.y * 8 + (threadIdx.x >> 5);
    int lane = threadIdx.x & 31;
    bool isq = (hh < NH);
    int col  = isq ? hh * HD : NH * HD + (hh - NH) * HD;
    __half* p = qkv + (long long)s * QKV_DIM + col + lane * 4;
    const float* w = (isq ? qn_w : kn_w) + lane * 4;
    const float* b = (isq ? qn_b : kn_b) + lane * 4;

    uint2 raw = *reinterpret_cast<const uint2*>(p);
    __half2 h01 = *reinterpret_cast<__half2*>(&raw.x);
    __half2 h23 = *reinterpret_cast<__half2*>(&raw.y);
    float v0 = __half2float(h01.x), v1 = __half2float(h01.y);
    float v2 = __half2float(h23.x), v3 = __half2float(h23.y);

    float mean = wredsum(v0 + v1 + v2 + v3) * (1.f / HD);
    float d0 = v0 - mean, d1 = v1 - mean, d2 = v2 - mean, d3 = v3 - mean;
    float var = wredsum(d0*d0 + d1*d1 + d2*d2 + d3*d3) * (1.f / HD);
    float rs = rsqrtf(var + EPS);

    float n0 = d0 * rs * w[0] + b[0];
    float n1 = d1 * rs * w[1] + b[1];
    float n2 = d2 * rs * w[2] + b[2];
    float n3 = d3 * rs * w[3] + b[3];

    const float* fc = fcos + (long long)s * (HD / 2) + lane * 2;
    const float* fs = fsin + (long long)s * (HD / 2) + lane * 2;
    float c0 = fc[0], s0 = fs[0], c1 = fc[1], s1 = fs[1];

    uint2 o;
    o.x = h2u(n0 * c0 - n1 * s0, n0 * s0 + n1 * c0);
    o.y = h2u(n2 * c1 - n3 * s1, n2 * s1 + n3 * c1);
    *reinterpret_cast<uint2*>(p) = o;
}

// ---------------- launcher ----------------
extern "C" void kernel_launch(void* const* d_in, const int* in_sizes, int n_in,
                              void* d_out, int out_size)
{
    const float* x           = (const float*)d_in[0];
    const float* fcos        = (const float*)d_in[1];
    const float* fsin        = (const float*)d_in[2];
    const float* wqkv        = (const float*)d_in[4];
    const float* wo          = (const float*)d_in[5];
    const float* qn_w        = (const float*)d_in[6];
    const float* qn_b        = (const float*)d_in[7];
    const float* kn_w        = (const float*)d_in[8];
    const float* kn_b        = (const float*)d_in[9];
    const float* attn_norm_w = (const float*)d_in[10];
    const float* ffn_norm_w  = (const float*)d_in[11];
    const float* w13         = (const float*)d_in[12];
    const float* w2          = (const float*)d_in[13];
    float* out = (float*)d_out;

    __half *h16, *qkv16, *o16, *gate16, *vt16;
    __half *wqkv16, *wo16, *w13_16, *w2_16;
    float *h2;
    cudaGetSymbolAddress((void**)&h16,     g_h16);
    cudaGetSymbolAddress((void**)&qkv16,   g_qkv16);
    cudaGetSymbolAddress((void**)&o16,     g_o16);
    cudaGetSymbolAddress((void**)&gate16,  g_gate16);
    cudaGetSymbolAddress((void**)&vt16,    g_vt16);
    cudaGetSymbolAddress((void**)&wqkv16,  g_wqkv16);
    cudaGetSymbolAddress((void**)&wo16,    g_wo16);
    cudaGetSymbolAddress((void**)&w13_16,  g_w13_16);
    cudaGetSymbolAddress((void**)&w2_16,   g_w2_16);
    cudaGetSymbolAddress((void**)&h2,      g_h2);

    static cudaStream_t sW = nullptr, sT = nullptr;
    static cudaEvent_t evRoot = nullptr, evW = nullptr, evWq = nullptr, evQ = nullptr, evT = nullptr;
    if (!sW) {
        cudaStreamCreateWithFlags(&sW, cudaStreamNonBlocking);
        cudaStreamCreateWithFlags(&sT, cudaStreamNonBlocking);
        cudaEventCreateWithFlags(&evRoot, cudaEventDisableTiming);
        cudaEventCreateWithFlags(&evW,    cudaEventDisableTiming);
        cudaEventCreateWithFlags(&evWq,   cudaEventDisableTiming);
        cudaEventCreateWithFlags(&evQ,    cudaEventDisableTiming);
        cudaEventCreateWithFlags(&evT,    cudaEventDisableTiming);
    }

    const int SMEM = NSTAGE * STAGE_B + 1024;
    const int FSMEM = 5 * 32768 + 256;
    cudaFuncSetAttribute((gemm_cp<float, false>),  cudaFuncAttributeMaxDynamicSharedMemorySize, SMEM);
    cudaFuncSetAttribute((gemm_cp<__half, false>), cudaFuncAttributeMaxDynamicSharedMemorySize, SMEM);
    cudaFuncSetAttribute((gemm_cp<__half, true>),  cudaFuncAttributeMaxDynamicSharedMemorySize, SMEM);
    cudaFuncSetAttribute(flash_attn, cudaFuncAttributeMaxDynamicSharedMemorySize, FSMEM);

    // ---- head: wqkv conversion runs ALONE on sT; rmsnorm in parallel on main ----
    cudaEventRecord(evRoot, 0);
    cudaStreamWaitEvent(sT, evRoot, 0);
    f2h_kernel<<<(QKV_DIM * (long long)DIM) / (256 * 16), 256, 0, sT>>>(
        wqkv, wqkv16, (long long)QKV_DIM * DIM);
    cudaEventRecord(evWq, sT);

    // sW: other weight conversions start AFTER wqkv (overlap the compute-bound qkv GEMM)
    cudaStreamWaitEvent(sW, evWq, 0);
    f2h_kernel<<<((long long)DIM * DIM) / (256 * 16), 256, 0, sW>>>(wo, wo16, (long long)DIM * DIM);
    f2h_w13<<<((long long)HID * DIM) / (256 * 8), 256, 0, sW>>>(w13, w13_16);
    f2h_kernel<<<((long long)DIM * HID) / (256 * 16), 256, 0, sW>>>(w2, w2_16, (long long)DIM * HID);
    cudaEventRecord(evW, sW);

    rmsnorm_h<<<S / 8, 256>>>(x, attn_norm_w, h16);
    cudaStreamWaitEvent(0, evWq, 0);

    gemm_cp<__half, false><<<dim3(S / BM, QKV_DIM / BN, 1), 128, SMEM>>>(
        h16, wqkv16, qkv16, DIM, DIM, DIM, QKV_DIM, nullptr);

    // fork: transpose_v in parallel with qknorm
    cudaEventRecord(evQ, 0);
    cudaStreamWaitEvent(sT, evQ, 0);
    transpose_v<<<dim3(S / 32, (NKV * HD) / 32), dim3(32, 8), 0, sT>>>(qkv16, vt16);
    cudaEventRecord(evT, sT);

    qknorm_rope_h<<<dim3(S, 3), 256>>>(qkv16, qn_w, qn_b, kn_w, kn_b, fcos, fsin);
    cudaStreamWaitEvent(0, evT, 0);

    // flash attention -> o16
    flash_attn<<<dim3(16, 16), 256, FSMEM>>>(qkv16, vt16, o16);

    cudaStreamWaitEvent(0, evW, 0);

    gemm_cp<float, false><<<dim3(S / BM, DIM / BN, 1), 128, SMEM>>>(
        o16, wo16, h2, DIM, DIM, DIM, DIM, x);

    rmsnorm_h<<<S / 8, 256>>>(h2, ffn_norm_w, h16);

    gemm_cp<__half, true><<<dim3(S / BM, (2 * HID) / BN, 1), 128, SMEM>>>(
        h16, w13_16, gate16, DIM, DIM, DIM, HID, nullptr);

    gemm_cp<float, false><<<dim3(S / BM, DIM / BN, 1), 128, SMEM>>>(
        gate16, w2_16, out, HID, HID, HID, DIM, h2);
}

// round 15
// speedup vs baseline: 1.0714x; 1.0199x over previous
#include <cuda_runtime.h>
#include <cuda_fp16.h>
#include <math.h>
#include <stdint.h>

#define S 2048
#define DIM 2048
#define NH 16
#define NKV 8
#define HD 128
#define HID 5632
#define QKV_DIM ((NH + 2*NKV) * HD)   // 4096
#define VOFF ((NH + NKV) * HD)        // 3072
#define EPS 1e-5f

// ---------------- scratch ----------------
__device__ __align__(256) __half g_h16[(size_t)S * DIM];
__device__ __align__(256) __half g_qkv16[(size_t)S * QKV_DIM];
__device__ __align__(256) __half g_o16[(size_t)S * DIM];
__device__ __align__(256) __half g_gate16[(size_t)S * HID];
__device__ __align__(256) __half g_vt16[(size_t)NKV * HD * S];
__device__ __align__(256) __half g_wqkv16[(size_t)QKV_DIM * DIM];
__device__ __align__(256) __half g_wo16[(size_t)DIM * DIM];
__device__ __align__(256) __half g_w13_16[(size_t)2 * HID * DIM];  // interleaved (w1_j,w3_j)
__device__ __align__(256) __half g_w2_16[(size_t)DIM * HID];
__device__ float g_h2[(size_t)S * DIM];
// split-KV flash partials: [h][part(16)][row(128)][col(128)]
__device__ __align__(256) float g_Opart[(size_t)NH * 16 * 128 * 128];
__device__ float g_mpart[(size_t)NH * 16 * 128];
__device__ float g_lpart[(size_t)NH * 16 * 128];

// ---------------- helpers ----------------
__device__ __forceinline__ uint32_t sm2u(const void* p) {
    uint32_t a;
    asm("{ .reg .u64 t; cvta.to.shared.u64 t, %1; cvt.u32.u64 %0, t; }" : "=r"(a) : "l"(p));
    return a;
}

__device__ __forceinline__ uint32_t smoff(uint32_t m, uint32_t k) {
    return (m >> 1) * 128u
         + (((((m & 1u) << 2) | (k >> 3)) ^ ((m >> 1) & 7u)) << 4)
         + (k & 7u) * 2u;
}
__device__ __forceinline__ uint32_t smoff256(uint32_t r, uint32_t chunk) {
    return r * 256u + (((chunk ^ (r & 7u)) & 15u) << 4);
}

__device__ __forceinline__ uint4 ldm4(uint32_t addr) {
    uint4 r;
    asm volatile("ldmatrix.sync.aligned.m8n8.x4.shared.b16 {%0,%1,%2,%3}, [%4];"
                 : "=r"(r.x), "=r"(r.y), "=r"(r.z), "=r"(r.w) : "r"(addr));
    return r;
}

__device__ __forceinline__ void mma_f16(float* c, const uint4& a, uint32_t b0, uint32_t b1) {
    asm volatile(
        "mma.sync.aligned.m16n8k16.row.col.f32.f16.f16.f32 "
        "{%0,%1,%2,%3}, {%4,%5,%6,%7}, {%8,%9}, {%0,%1,%2,%3};"
        : "+f"(c[0]), "+f"(c[1]), "+f"(c[2]), "+f"(c[3])
        : "r"(a.x), "r"(a.y), "r"(a.z), "r"(a.w), "r"(b0), "r"(b1));
}

__device__ __forceinline__ void cpasync16(uint32_t dst, const void* src) {
    asm volatile("cp.async.cg.shared.global [%0], [%1], 16;" :: "r"(dst), "l"(src) : "memory");
}
__device__ __forceinline__ void cpcommit() {
    asm volatile("cp.async.commit_group;" ::: "memory");
}
template<int N> __device__ __forceinline__ void cpwait() {
    asm volatile("cp.async.wait_group %0;" :: "n"(N) : "memory");
}

__device__ __forceinline__ uint32_t h2u(float a, float b) {
    __half2 h = __floats2half2_rn(a, b);
    return *reinterpret_cast<uint32_t*>(&h);
}
__device__ __forceinline__ void st2(float* p, float a, float b) {
    *reinterpret_cast<float2*>(p) = make_float2(a, b);
}
__device__ __forceinline__ void st2(__half* p, float a, float b) {
    *reinterpret_cast<__half2*>(p) = __floats2half2_rn(a, b);
}
__device__ __forceinline__ float wredsum(float v) {
    #pragma unroll
    for (int o = 16; o; o >>= 1) v += __shfl_xor_sync(0xffffffffu, v, o);
    return v;
}

// ---------------- fp16 cp.async NT GEMM (2x2 warps, 64x64 warp tiles) ----------------
#define BM 128
#define BN 128
#define BK 32
#define ATILE_B 8192
#define STAGE_B 16384
#define NSTAGE 4

template<typename OutT, bool SWIGLU>
__global__ void __launch_bounds__(128, 2)
gemm_cp(const __half* __restrict__ A, const __half* __restrict__ B, OutT* __restrict__ C,
        int K, int lda, int ldb, int ldc, const float* __restrict__ res)
{
    int bm = blockIdx.x * BM;
    int bn = blockIdx.y * BN;

    extern __shared__ unsigned char smraw[];
    uint32_t smB = (sm2u(smraw) + 1023) & ~1023u;

    int tid  = threadIdx.x;
    int lane = tid & 31;
    int warp = tid >> 5;
    int wm = warp >> 1;
    int wn = warp & 1;

    int nCh = K / BK;

    int pr  = tid >> 2;
    int kc0 = (tid & 3) * 8;
    const __half* Ag = A + (long long)bm * lda;
    const __half* Bg = B + (long long)bn * ldb;
    uint32_t so[4];
    #pragma unroll
    for (int q = 0; q < 4; ++q) so[q] = smoff(pr + 32 * q, kc0);

    auto issue = [&](int c) {
        uint32_t aB = smB + (c & (NSTAGE - 1)) * STAGE_B;
        uint32_t bB = aB + ATILE_B;
        int k0 = c * BK + kc0;
        #pragma unroll
        for (int q = 0; q < 4; ++q)
            cpasync16(aB + so[q], Ag + (long long)(pr + 32 * q) * lda + k0);
        #pragma unroll
        for (int q = 0; q < 4; ++q)
            cpasync16(bB + so[q], Bg + (long long)(pr + 32 * q) * ldb + k0);
        cpcommit();
    };

    uint32_t aAdr[4], bAdr[4];
    {
        int mi = lane >> 3;
        int ra = (lane & 7) + (mi & 1) * 8;
        int ka = (mi >> 1) * 8;
        #pragma unroll
        for (int g = 0; g < 4; ++g) aAdr[g] = smoff(wm * 64 + g * 16 + ra, ka);
        int rb = (lane & 7) + (mi >> 1) * 8;
        int kb = (mi & 1) * 8;
        #pragma unroll
        for (int g = 0; g < 4; ++g) bAdr[g] = smoff(wn * 64 + g * 16 + rb, kb);
    }

    float acc[4][8][4];
    #pragma unroll
    for (int a = 0; a < 4; ++a)
        #pragma unroll
        for (int b = 0; b < 8; ++b)
            #pragma unroll
            for (int c = 0; c < 4; ++c) acc[a][b][c] = 0.f;

    #pragma unroll
    for (int c = 0; c < 3; ++c) {
        if (c < nCh) issue(c);
        else cpcommit();
    }

    for (int it = 0; it < nCh; ++it) {
        cpwait<2>();
        __syncthreads();
        if (it + 3 < nCh) issue(it + 3);
        else cpcommit();

        uint32_t aB = smB + (it & (NSTAGE - 1)) * STAGE_B;
        uint32_t bB = aB + ATILE_B;

        #pragma unroll
        for (int ks = 0; ks < 2; ++ks) {
            uint32_t kx = ks ? 32u : 0u;
            uint4 av[4], bv[4];
            #pragma unroll
            for (int g = 0; g < 4; ++g) av[g] = ldm4(aB + (aAdr[g] ^ kx));
            #pragma unroll
            for (int g = 0; g < 4; ++g) bv[g] = ldm4(bB + (bAdr[g] ^ kx));
            #pragma unroll
            for (int mi = 0; mi < 4; ++mi) {
                #pragma unroll
                for (int nj = 0; nj < 8; ++nj) {
                    uint32_t b0 = (nj & 1) ? bv[nj >> 1].z : bv[nj >> 1].x;
                    uint32_t b1 = (nj & 1) ? bv[nj >> 1].w : bv[nj >> 1].y;
                    mma_f16(acc[mi][nj], av[mi], b0, b1);
                }
            }
        }
    }
    cpwait<0>();

    int grp = lane >> 2;
    int tg  = lane & 3;

    if (SWIGLU) {
        __syncthreads();
        __half* buf = reinterpret_cast<__half*>(smraw);
        #pragma unroll
        for (int mi = 0; mi < 4; ++mi) {
            int lr = wm * 64 + mi * 16 + grp;
            #pragma unroll
            for (int nj = 0; nj < 8; ++nj) {
                int pl = wn * 32 + nj * 4 + tg;
                float a0 = acc[mi][nj][0], b0v = acc[mi][nj][1];
                float a1 = acc[mi][nj][2], b1v = acc[mi][nj][3];
                buf[lr * 72 + pl]       = __float2half_rn(a0 * b0v / (1.f + expf(-a0)));
                buf[(lr + 8) * 72 + pl] = __float2half_rn(a1 * b1v / (1.f + expf(-a1)));
            }
        }
        __syncthreads();
        __half* Ch = (__half*)C;
        __half* dst = Ch + (long long)(bm + tid) * ldc + (bn >> 1);
        const __half* srcb = buf + tid * 72;
        #pragma unroll
        for (int q = 0; q < 8; ++q)
            *reinterpret_cast<uint4*>(dst + q * 8) =
                *reinterpret_cast<const uint4*>(srcb + q * 8);
    } else {
        #pragma unroll
        for (int mi = 0; mi < 4; ++mi) {
            long long r0 = bm + wm * 64 + mi * 16 + grp;
            #pragma unroll
            for (int nj = 0; nj < 8; ++nj) {
                int c0 = bn + wn * 64 + nj * 8 + tg * 2;
                float v0 = acc[mi][nj][0], v1 = acc[mi][nj][1];
                float v2 = acc[mi][nj][2], v3 = acc[mi][nj][3];
                if (res) {
                    float2 r01 = *reinterpret_cast<const float2*>(&res[r0 * ldc + c0]);
                    float2 r23 = *reinterpret_cast<const float2*>(&res[(r0 + 8) * ldc + c0]);
                    v0 += r01.x; v1 += r01.y; v2 += r23.x; v3 += r23.y;
                }
                st2(&C[r0 * ldc + c0],       v0, v1);
                st2(&C[(r0 + 8) * ldc + c0], v2, v3);
            }
        }
    }
}

// ---------------- fused flash attention, split-KV load balancing ----------------
// grid (24, 16): per head, items 0..15 = halves of qb 15..8 (split), 16..23 =
// unsplit qb 7..0. Split items emit unnormalized fp32 partials + (m,l);
// combine_kernel merges. Heavy items scheduled first.
#define CSC 0.1275447941f   // (1/sqrt(128)) * log2(e)

__global__ void __launch_bounds__(256)
flash_attn(const __half* __restrict__ qkv, const __half* __restrict__ vt,
           __half* __restrict__ o,
           float* __restrict__ Opart, float* __restrict__ mpart, float* __restrict__ lpart)
{
    int i = blockIdx.x;
    int h = blockIdx.y;
    int qb, kvlo, kvhi, part = 0;
    bool split;
    if (i < 16) {
        qb = 15 - (i >> 1);
        int nb = qb + 1, sp = nb >> 1;
        split = true;
        if (i & 1) { kvlo = sp; kvhi = nb; } else { kvlo = 0; kvhi = sp; }
        part = (qb - 8) * 2 + (i & 1);
    } else {
        qb = 23 - i;
        kvlo = 0; kvhi = qb + 1;
        split = false;
    }

    extern __shared__ unsigned char smraw[];
    uint32_t smQ = (sm2u(smraw) + 255) & ~255u;
    uint32_t smK = smQ + 32768;
    uint32_t smV = smK + 2 * 32768;

    int tid  = threadIdx.x;
    int lane = tid & 31;
    int warp = tid >> 5;
    int wrow = warp * 16;
    int grp  = lane >> 2;
    int tg   = lane & 3;

    const __half* Qg = qkv + (size_t)(qb * 128) * QKV_DIM + h * HD;
    const __half* Kg = qkv + NH * HD + (h >> 1) * HD;
    const __half* Vg = vt + (size_t)((h >> 1) * HD) * S;

    int prow = tid >> 1;
    int pc0  = (tid & 1) * 8;

    auto issueQ = [&]() {
        #pragma unroll
        for (int c = 0; c < 8; ++c) {
            int ch = pc0 + c;
            cpasync16(smQ + smoff256(prow, ch), Qg + (size_t)prow * QKV_DIM + ch * 8);
        }
    };
    auto issueKV = [&](int b) {
        uint32_t kB = smK + (b & 1) * 32768;
        uint32_t vB = smV + (b & 1) * 32768;
        #pragma unroll
        for (int c = 0; c < 8; ++c) {
            int ch = pc0 + c;
            uint32_t off = smoff256(prow, ch);
            cpasync16(kB + off, Kg + (size_t)(b * 128 + prow) * QKV_DIM + ch * 8);
            cpasync16(vB + off, Vg + (size_t)prow * S + b * 128 + ch * 8);
        }
    };

    issueQ();
    issueKV(kvlo);
    cpcommit();

    int mi   = lane >> 3;
    int frow = (lane & 7) + (mi & 1) * 8;
    int fkc  = (mi >> 1);
    int brow = (lane & 7) + (mi >> 1) * 8;
    int bkc  = (mi & 1);

    float m0 = -1e30f, m1 = -1e30f, l0 = 0.f, l1 = 0.f;
    float O[16][4];
    #pragma unroll
    for (int j = 0; j < 16; ++j)
        #pragma unroll
        for (int c = 0; c < 4; ++c) O[j][c] = 0.f;

    uint4 qf[8];

    for (int b = kvlo; b < kvhi; ++b) {
        cpwait<0>();
        __syncthreads();

        if (b == kvlo) {
            #pragma unroll
            for (int ks = 0; ks < 8; ++ks)
                qf[ks] = ldm4(smQ + smoff256(wrow + frow, ks * 2 + fkc));
        }
        if (b + 1 < kvhi) { issueKV(b + 1); cpcommit(); }

        uint32_t kB = smK + (b & 1) * 32768;
        uint32_t vB = smV + (b & 1) * 32768;

        float Sv[16][4];
        #pragma unroll
        for (int j = 0; j < 16; ++j)
            #pragma unroll
            for (int c = 0; c < 4; ++c) Sv[j][c] = 0.f;

        #pragma unroll
        for (int ks = 0; ks < 8; ++ks) {
            #pragma unroll
            for (int g = 0; g < 8; ++g) {
                uint4 bv = ldm4(kB + smoff256(g * 16 + brow, ks * 2 + bkc));
                mma_f16(Sv[2 * g],     qf[ks], bv.x, bv.y);
                mma_f16(Sv[2 * g + 1], qf[ks], bv.z, bv.w);
            }
        }

        if (b == qb) {
            int r0 = wrow + grp;
            #pragma unroll
            for (int j = 0; j < 16; ++j) {
                int c0 = j * 8 + tg * 2;
                if (c0     > r0)     Sv[j][0] = -1e30f;
                if (c0 + 1 > r0)     Sv[j][1] = -1e30f;
                if (c0     > r0 + 8) Sv[j][2] = -1e30f;
                if (c0 + 1 > r0 + 8) Sv[j][3] = -1e30f;
            }
        }

        float bm0 = -1e30f, bm1 = -1e30f;
        #pragma unroll
        for (int j = 0; j < 16; ++j) {
            bm0 = fmaxf(bm0, fmaxf(Sv[j][0], Sv[j][1]));
            bm1 = fmaxf(bm1, fmaxf(Sv[j][2], Sv[j][3]));
        }
        bm0 = fmaxf(bm0, __shfl_xor_sync(0xffffffffu, bm0, 1));
        bm0 = fmaxf(bm0, __shfl_xor_sync(0xffffffffu, bm0, 2));
        bm1 = fmaxf(bm1, __shfl_xor_sync(0xffffffffu, bm1, 1));
        bm1 = fmaxf(bm1, __shfl_xor_sync(0xffffffffu, bm1, 2));

        float nm0 = fmaxf(m0, bm0), nm1 = fmaxf(m1, bm1);
        float sc0 = exp2f((m0 - nm0) * CSC), sc1 = exp2f((m1 - nm1) * CSC);
        m0 = nm0; m1 = nm1;

        float rs0 = 0.f, rs1 = 0.f;
        #pragma unroll
        for (int j = 0; j < 16; ++j) {
            Sv[j][0] = exp2f((Sv[j][0] - nm0) * CSC); rs0 += Sv[j][0];
            Sv[j][1] = exp2f((Sv[j][1] - nm0) * CSC); rs0 += Sv[j][1];
            Sv[j][2] = exp2f((Sv[j][2] - nm1) * CSC); rs1 += Sv[j][2];
            Sv[j][3] = exp2f((Sv[j][3] - nm1) * CSC); rs1 += Sv[j][3];
        }
        l0 = l0 * sc0 + rs0;
        l1 = l1 * sc1 + rs1;

        #pragma unroll
        for (int j = 0; j < 16; ++j) {
            O[j][0] *= sc0; O[j][1] *= sc0;
            O[j][2] *= sc1; O[j][3] *= sc1;
        }

        #pragma unroll
        for (int ks = 0; ks < 8; ++ks) {
            uint4 pa;
            pa.x = h2u(Sv[2 * ks][0],     Sv[2 * ks][1]);
            pa.y = h2u(Sv[2 * ks][2],     Sv[2 * ks][3]);
            pa.z = h2u(Sv[2 * ks + 1][0], Sv[2 * ks + 1][1]);
            pa.w = h2u(Sv[2 * ks + 1][2], Sv[2 * ks + 1][3]);
            #pragma unroll
            for (int g = 0; g < 8; ++g) {
                uint4 bv = ldm4(vB + smoff256(g * 16 + brow, ks * 2 + bkc));
                mma_f16(O[2 * g],     pa, bv.x, bv.y);
                mma_f16(O[2 * g + 1], pa, bv.z, bv.w);
            }
        }
    }

    // quad-reduce l
    l0 += __shfl_xor_sync(0xffffffffu, l0, 1);
    l0 += __shfl_xor_sync(0xffffffffu, l0, 2);
    l1 += __shfl_xor_sync(0xffffffffu, l1, 1);
    l1 += __shfl_xor_sync(0xffffffffu, l1, 2);

    int r0 = wrow + grp;
    if (!split) {
        float inv0 = 1.f / l0, inv1 = 1.f / l1;
        __half* o0 = o + (size_t)(qb * 128 + r0) * DIM + h * HD;
        __half* o1 = o0 + 8 * DIM;
        #pragma unroll
        for (int j = 0; j < 16; ++j) {
            int c0 = j * 8 + tg * 2;
            st2(o0 + c0, O[j][0] * inv0, O[j][1] * inv0);
            st2(o1 + c0, O[j][2] * inv1, O[j][3] * inv1);
        }
    } else {
        float* Op = Opart + (size_t)(h * 16 + part) * 128 * 128;
        #pragma unroll
        for (int j = 0; j < 16; ++j) {
            int c0 = j * 8 + tg * 2;
            st2(&Op[r0 * 128 + c0],       O[j][0], O[j][1]);
            st2(&Op[(r0 + 8) * 128 + c0], O[j][2], O[j][3]);
        }
        if (tg == 0) {
            int base = (h * 16 + part) * 128;
            mpart[base + r0]     = m0;
            lpart[base + r0]     = l0;
            mpart[base + r0 + 8] = m1;
            lpart[base + r0 + 8] = l1;
        }
    }
}

// combine split-KV partials: grid (8 qb, 16 h), 128 threads (one row each)
__global__ void combine_kernel(const float* __restrict__ Opart,
                               const float* __restrict__ mpart,
                               const float* __restrict__ lpart,
                               __half* __restrict__ o)
{
    int qb  = 8 + blockIdx.x;
    int h   = blockIdx.y;
    int row = threadIdx.x;
    int p0  = (qb - 8) * 2;
    int b0  = (h * 16 + p0) * 128 + row;
    int b1  = b0 + 128;

    float m0 = mpart[b0], m1 = mpart[b1];
    float l0 = lpart[b0], l1 = lpart[b1];
    float M  = fmaxf(m0, m1);
    float w0 = exp2f((m0 - M) * CSC), w1 = exp2f((m1 - M) * CSC);
    float inv = 1.f / (l0 * w0 + l1 * w1);

    const float* O0 = Opart + (size_t)(h * 16 + p0) * 128 * 128 + row * 128;
    const float* O1 = O0 + 128 * 128;
    __half* dst = o + (size_t)(qb * 128 + row) * DIM + h * HD;

    #pragma unroll
    for (int c = 0; c < 128; c += 4) {
        float4 a = *reinterpret_cast<const float4*>(O0 + c);
        float4 b = *reinterpret_cast<const float4*>(O1 + c);
        uint2 u;
        u.x = h2u((a.x * w0 + b.x * w1) * inv, (a.y * w0 + b.y * w1) * inv);
        u.y = h2u((a.z * w0 + b.z * w1) * inv, (a.w * w0 + b.w * w1) * inv);
        *reinterpret_cast<uint2*>(dst + c) = u;
    }
}

// ---------------- fp32 -> fp16, ILP 4 ----------------
__global__ void f2h_kernel(const float* __restrict__ in, __half* __restrict__ out, long long n)
{
    long long i = ((long long)blockIdx.x * 256 + threadIdx.x) * 16;
    if (i >= n) return;
    float4 v[4];
    #pragma unroll
    for (int q = 0; q < 4; ++q)
        v[q] = *reinterpret_cast<const float4*>(in + i + q * 4);
    #pragma unroll
    for (int q = 0; q < 2; ++q) {
        uint4 o;
        o.x = h2u(v[2*q].x,   v[2*q].y);
        o.y = h2u(v[2*q].z,   v[2*q].w);
        o.z = h2u(v[2*q+1].x, v[2*q+1].y);
        o.w = h2u(v[2*q+1].z, v[2*q+1].w);
        *reinterpret_cast<uint4*>(out + i + q * 8) = o;
    }
}

__global__ void f2h_w13(const float* __restrict__ in, __half* __restrict__ out)
{
    long long g = ((long long)blockIdx.x * 256 + threadIdx.x) * 8;
    if (g >= (long long)HID * DIM) return;
    long long j = g / DIM;
    long long c = g - j * DIM;
    #pragma unroll
    for (int s = 0; s < 2; ++s) {
        const float* src = in + ((s ? HID : 0) + j) * (long long)DIM + c;
        float4 a = *reinterpret_cast<const float4*>(src);
        float4 b = *reinterpret_cast<const float4*>(src + 4);
        uint4 o;
        o.x = h2u(a.x, a.y); o.y = h2u(a.z, a.w);
        o.z = h2u(b.x, b.y); o.w = h2u(b.z, b.w);
        *reinterpret_cast<uint4*>(out + (2 * j + s) * (long long)DIM + c) = o;
    }
}

// ---------------- V transpose ----------------
__global__ void transpose_v(const __half* __restrict__ qkv, __half* __restrict__ vt)
{
    __shared__ float t[32][33];
    int s0 = blockIdx.x * 32;
    int d0 = blockIdx.y * 32;
    int tx = threadIdx.x, ty = threadIdx.y;
    #pragma unroll
    for (int j = 0; j < 32; j += 8)
        t[ty + j][tx] = __half2float(qkv[(long long)(s0 + ty + j) * QKV_DIM + VOFF + d0 + tx]);
    __syncthreads();
    #pragma unroll
    for (int j = 0; j < 32; j += 8)
        vt[(long long)(d0 + ty + j) * S + s0 + tx] = __float2half_rn(t[tx][ty + j]);
}

// ---------------- warp-per-row rmsnorm ----------------
__global__ void rmsnorm_h(const float* __restrict__ x, const float* __restrict__ w,
                          __half* __restrict__ out)
{
    int row  = blockIdx.x * 8 + (threadIdx.x >> 5);
    int lane = threadIdx.x & 31;
    const float* xr = x + (long long)row * DIM;

    float s = 0.f;
    float4 v[16];
    #pragma unroll
    for (int i = 0; i < 16; ++i) {
        v[i] = *reinterpret_cast<const float4*>(xr + lane * 4 + i * 128);
        s += v[i].x * v[i].x + v[i].y * v[i].y + v[i].z * v[i].z + v[i].w * v[i].w;
    }
    s = wredsum(s);
    float inv = rsqrtf(s / (float)DIM + EPS);

    __half* orow = out + (long long)row * DIM;
    #pragma unroll
    for (int i = 0; i < 16; ++i) {
        int c = lane * 4 + i * 128;
        uint2 o;
        o.x = h2u(v[i].x * inv * w[c],     v[i].y * inv * w[c + 1]);
        o.y = h2u(v[i].z * inv * w[c + 2], v[i].w * inv * w[c + 3]);
        *reinterpret_cast<uint2*>(orow + c) = o;
    }
}

// ---------------- warp-per-head layernorm + rope ----------------
__global__ void qknorm_rope_h(__half* __restrict__ qkv,
                              const float* __restrict__ qn_w, const float* __restrict__ qn_b,
                              const float* __restrict__ kn_w, const float* __restrict__ kn_b,
                              const float* __restrict__ fcos, const float* __restrict__ fsin)
{
    int s    = blockIdx.x;
    int hh   = blockIdx.y * 8 + (threadIdx.x >> 5);
    int lane = threadIdx.x & 31;
    bool isq = (hh < NH);
    int col  = isq ? hh * HD : NH * HD + (hh - NH) * HD;
    __half* p = qkv + (long long)s * QKV_DIM + col + lane * 4;
    const float* w = (isq ? qn_w : kn_w) + lane * 4;
    const float* b = (isq ? qn_b : kn_b) + lane * 4;

    uint2 raw = *reinterpret_cast<const uint2*>(p);
    __half2 h01 = *reinterpret_cast<__half2*>(&raw.x);
    __half2 h23 = *reinterpret_cast<__half2*>(&raw.y);
    float v0 = __half2float(h01.x), v1 = __half2float(h01.y);
    float v2 = __half2float(h23.x), v3 = __half2float(h23.y);

    float mean = wredsum(v0 + v1 + v2 + v3) * (1.f / HD);
    float d0 = v0 - mean, d1 = v1 - mean, d2 = v2 - mean, d3 = v3 - mean;
    float var = wredsum(d0*d0 + d1*d1 + d2*d2 + d3*d3) * (1.f / HD);
    float rs = rsqrtf(var + EPS);

    float n0 = d0 * rs * w[0] + b[0];
    float n1 = d1 * rs * w[1] + b[1];
    float n2 = d2 * rs * w[2] + b[2];
    float n3 = d3 * rs * w[3] + b[3];

    const float* fc = fcos + (long long)s * (HD / 2) + lane * 2;
    const float* fs = fsin + (long long)s * (HD / 2) + lane * 2;
    float c0 = fc[0], s0 = fs[0], c1 = fc[1], s1 = fs[1];

    uint2 o;
    o.x = h2u(n0 * c0 - n1 * s0, n0 * s0 + n1 * c0);
    o.y = h2u(n2 * c1 - n3 * s1, n2 * s1 + n3 * c1);
    *reinterpret_cast<uint2*>(p) = o;
}

// ---------------- launcher ----------------
extern "C" void kernel_launch(void* const* d_in, const int* in_sizes, int n_in,
                              void* d_out, int out_size)
{
    const float* x           = (const float*)d_in[0];
    const float* fcos        = (const float*)d_in[1];
    const float* fsin        = (const float*)d_in[2];
    const float* wqkv        = (const float*)d_in[4];
    const float* wo          = (const float*)d_in[5];
    const float* qn_w        = (const float*)d_in[6];
    const float* qn_b        = (const float*)d_in[7];
    const float* kn_w        = (const float*)d_in[8];
    const float* kn_b        = (const float*)d_in[9];
    const float* attn_norm_w = (const float*)d_in[10];
    const float* ffn_norm_w  = (const float*)d_in[11];
    const float* w13         = (const float*)d_in[12];
    const float* w2          = (const float*)d_in[13];
    float* out = (float*)d_out;

    __half *h16, *qkv16, *o16, *gate16, *vt16;
    __half *wqkv16, *wo16, *w13_16, *w2_16;
    float *h2, *Opart, *mpart, *lpart;
    cudaGetSymbolAddress((void**)&h16,     g_h16);
    cudaGetSymbolAddress((void**)&qkv16,   g_qkv16);
    cudaGetSymbolAddress((void**)&o16,     g_o16);
    cudaGetSymbolAddress((void**)&gate16,  g_gate16);
    cudaGetSymbolAddress((void**)&vt16,    g_vt16);
    cudaGetSymbolAddress((void**)&wqkv16,  g_wqkv16);
    cudaGetSymbolAddress((void**)&wo16,    g_wo16);
    cudaGetSymbolAddress((void**)&w13_16,  g_w13_16);
    cudaGetSymbolAddress((void**)&w2_16,   g_w2_16);
    cudaGetSymbolAddress((void**)&h2,      g_h2);
    cudaGetSymbolAddress((void**)&Opart,   g_Opart);
    cudaGetSymbolAddress((void**)&mpart,   g_mpart);
    cudaGetSymbolAddress((void**)&lpart,   g_lpart);

    static cudaStream_t sW = nullptr, sT = nullptr;
    static cudaEvent_t evRoot = nullptr, evW = nullptr, evWq = nullptr, evQ = nullptr, evT = nullptr;
    if (!sW) {
        cudaStreamCreateWithFlags(&sW, cudaStreamNonBlocking);
        cudaStreamCreateWithFlags(&sT, cudaStreamNonBlocking);
        cudaEventCreateWithFlags(&evRoot, cudaEventDisableTiming);
        cudaEventCreateWithFlags(&evW,    cudaEventDisableTiming);
        cudaEventCreateWithFlags(&evWq,   cudaEventDisableTiming);
        cudaEventCreateWithFlags(&evQ,    cudaEventDisableTiming);
        cudaEventCreateWithFlags(&evT,    cudaEventDisableTiming);
    }

    const int SMEM = NSTAGE * STAGE_B + 1024;
    const int FSMEM = 5 * 32768 + 256;
    cudaFuncSetAttribute((gemm_cp<float, false>),  cudaFuncAttributeMaxDynamicSharedMemorySize, SMEM);
    cudaFuncSetAttribute((gemm_cp<__half, false>), cudaFuncAttributeMaxDynamicSharedMemorySize, SMEM);
    cudaFuncSetAttribute((gemm_cp<__half, true>),  cudaFuncAttributeMaxDynamicSharedMemorySize, SMEM);
    cudaFuncSetAttribute(flash_attn, cudaFuncAttributeMaxDynamicSharedMemorySize, FSMEM);

    // ---- head: wqkv conversion ALONE on sT; rmsnorm in parallel on main ----
    cudaEventRecord(evRoot, 0);
    cudaStreamWaitEvent(sT, evRoot, 0);
    f2h_kernel<<<(QKV_DIM * (long long)DIM) / (256 * 16), 256, 0, sT>>>(
        wqkv, wqkv16, (long long)QKV_DIM * DIM);
    cudaEventRecord(evWq, sT);

    cudaStreamWaitEvent(sW, evWq, 0);
    f2h_kernel<<<((long long)DIM * DIM) / (256 * 16), 256, 0, sW>>>(wo, wo16, (long long)DIM * DIM);
    f2h_w13<<<((long long)HID * DIM) / (256 * 8), 256, 0, sW>>>(w13, w13_16);
    f2h_kernel<<<((long long)DIM * HID) / (256 * 16), 256, 0, sW>>>(w2, w2_16, (long long)DIM * HID);
    cudaEventRecord(evW, sW);

    rmsnorm_h<<<S / 8, 256>>>(x, attn_norm_w, h16);
    cudaStreamWaitEvent(0, evWq, 0);

    gemm_cp<__half, false><<<dim3(S / BM, QKV_DIM / BN, 1), 128, SMEM>>>(
        h16, wqkv16, qkv16, DIM, DIM, DIM, QKV_DIM, nullptr);

    // fork: transpose_v in parallel with qknorm
    cudaEventRecord(evQ, 0);
    cudaStreamWaitEvent(sT, evQ, 0);
    transpose_v<<<dim3(S / 32, (NKV * HD) / 32), dim3(32, 8), 0, sT>>>(qkv16, vt16);
    cudaEventRecord(evT, sT);

    qknorm_rope_h<<<dim3(S, 3), 256>>>(qkv16, qn_w, qn_b, kn_w, kn_b, fcos, fsin);
    cudaStreamWaitEvent(0, evT, 0);

    // split-KV flash attention -> o16 / partials, then combine
    flash_attn<<<dim3(24, 16), 256, FSMEM>>>(qkv16, vt16, o16, Opart, mpart, lpart);
    combine_kernel<<<dim3(8, 16), 128>>>(Opart, mpart, lpart, o16);

    cudaStreamWaitEvent(0, evW, 0);

    gemm_cp<float, false><<<dim3(S / BM, DIM / BN, 1), 128, SMEM>>>(
        o16, wo16, h2, DIM, DIM, DIM, DIM, x);

    rmsnorm_h<<<S / 8, 256>>>(h2, ffn_norm_w, h16);

    gemm_cp<__half, true><<<dim3(S / BM, (2 * HID) / BN, 1), 128, SMEM>>>(
        h16, w13_16, gate16, DIM, DIM, DIM, HID, nullptr);

    gemm_cp<float, false><<<dim3(S / BM, DIM / BN, 1), 128, SMEM>>>(
        gate16, w2_16, out, HID, HID, HID, DIM, h2);
}